// round 2
// baseline (speedup 1.0000x reference)
#include <cuda_runtime.h>
#include <cuda_bf16.h>
#include <math.h>

#define N_NODES 50000
#define N_EDGES 1000000
#define N_GRAPHS 256
#define ORIG 92
#define ATOM 64
#define NBR 41
#define KTOT (2*ATOM + NBR)   // 169
#define COUT (2*ATOM)         // 128
#define EPSV 1e-5f

// ---------------- scratch (device globals; no allocation allowed) ----------------
__device__ float g_atom_fea[(size_t)N_NODES * ATOM];
__device__ float g_gated[(size_t)N_EDGES * COUT];          // 512 MB
__device__ float g_summed[(size_t)N_NODES * ATOM];
__device__ float g_h[(size_t)N_NODES * ATOM];
__device__ float g_logits[N_NODES];
__device__ float g_bn1_acc[2 * COUT];                      // [sum(128), sumsq(128)]
__device__ float g_bn1_scale[COUT];
__device__ float g_bn1_shift[COUT];
__device__ float g_bn2_acc[2 * ATOM];                      // [sum(64), sumsq(64)]
__device__ float g_bn2_scale[ATOM];
__device__ float g_bn2_shift[ATOM];

// ---------------- Kernel A: atom_fea = x @ emb_W + emb_b + lower_f ----------------
#define A_NPB 256
__global__ void atomfea_kernel(const float* __restrict__ x,
                               const float* __restrict__ embW,
                               const float* __restrict__ embb,
                               const float* __restrict__ lower) {
    __shared__ float Wsm[ORIG * ATOM];       // 23.5 KB
    __shared__ float xrow[4][ORIG];
    for (int i = threadIdx.x; i < ORIG * ATOM; i += 256) Wsm[i] = embW[i];
    int c = threadIdx.x & 63;
    int q = threadIdx.x >> 6;                 // 0..3
    float bias = embb[c];
    for (int it = 0; it < A_NPB / 4; ++it) {
        int nbase = blockIdx.x * A_NPB + it * 4;
        __syncthreads();
        for (int i = threadIdx.x; i < 4 * ORIG; i += 256) {
            int nn = nbase + i / ORIG;
            xrow[i / ORIG][i % ORIG] = (nn < N_NODES) ? x[(size_t)nn * ORIG + (i % ORIG)] : 0.f;
        }
        __syncthreads();
        int n = nbase + q;
        if (n < N_NODES) {
            float s = bias;
            #pragma unroll 4
            for (int k = 0; k < ORIG; ++k) s = fmaf(xrow[q][k], Wsm[k * ATOM + c], s);
            g_atom_fea[(size_t)n * ATOM + c] = s + lower[(size_t)n * ATOM + c];
        }
    }
}

// ---------------- Kernel B1: edge GEMM + BN1 partial stats ----------------
// total[e] = [atom_fea[src], atom_fea[dst], edge_attr[e]] (169)
// gated_pre = total @ fc_W + fc_b  -> store; accumulate per-channel sum/sumsq
#define BE 128
#define B1_SMEM (KTOT*COUT*4 + BE*KTOT*4)   // 86528 + 86528 = 173056 bytes

__global__ void edge_gemm_kernel(const float* __restrict__ edge_attr,
                                 const int* __restrict__ ei,
                                 const float* __restrict__ fcW,
                                 const float* __restrict__ fcb) {
    extern __shared__ float sm[];
    float* Wsm = sm;                 // [KTOT][COUT]
    float* Tsm = sm + KTOT * COUT;   // [BE][KTOT]  (later reused for reduction)

    for (int i = threadIdx.x; i < KTOT * COUT; i += 256) Wsm[i] = fcW[i];

    int e0 = blockIdx.x * BE;
    for (int i = threadIdx.x; i < BE * KTOT; i += 256) {
        int le = i / KTOT;
        int k  = i - le * KTOT;
        int e  = e0 + le;
        float v = 0.f;
        if (e < N_EDGES) {
            if (k < ATOM)            v = g_atom_fea[(size_t)ei[e] * ATOM + k];
            else if (k < 2 * ATOM)   v = g_atom_fea[(size_t)ei[N_EDGES + e] * ATOM + (k - ATOM)];
            else                     v = edge_attr[(size_t)e * NBR + (k - 2 * ATOM)];
        }
        Tsm[le * KTOT + k] = v;
    }
    __syncthreads();

    int te = threadIdx.x >> 4;   // 0..15 (edge groups of 8)
    int tc = threadIdx.x & 15;   // 0..15 (channel groups of 8)
    float acc[8][8];
    #pragma unroll
    for (int i = 0; i < 8; ++i)
        #pragma unroll
        for (int j = 0; j < 8; ++j) acc[i][j] = 0.f;

    const float* Trow = Tsm + te * 8 * KTOT;
    for (int k = 0; k < KTOT; ++k) {
        float a[8];
        #pragma unroll
        for (int i = 0; i < 8; ++i) a[i] = Trow[i * KTOT + k];
        float4 w0 = *(const float4*)(Wsm + k * COUT + tc * 8);
        float4 w1 = *(const float4*)(Wsm + k * COUT + tc * 8 + 4);
        float w[8] = {w0.x, w0.y, w0.z, w0.w, w1.x, w1.y, w1.z, w1.w};
        #pragma unroll
        for (int i = 0; i < 8; ++i)
            #pragma unroll
            for (int j = 0; j < 8; ++j)
                acc[i][j] = fmaf(a[i], w[j], acc[i][j]);
    }
    __syncthreads();   // Tsm free now; reuse for reduction buffers

    float b[8];
    #pragma unroll
    for (int j = 0; j < 8; ++j) b[j] = fcb[tc * 8 + j];

    float psum[8], psq[8];
    #pragma unroll
    for (int j = 0; j < 8; ++j) { psum[j] = 0.f; psq[j] = 0.f; }

    #pragma unroll
    for (int i = 0; i < 8; ++i) {
        int e = e0 + te * 8 + i;
        if (e < N_EDGES) {
            #pragma unroll
            for (int j = 0; j < 8; ++j) {
                float v = acc[i][j] + b[j];
                acc[i][j] = v;
                psum[j] += v;
                psq[j]  += v * v;
            }
            float4 s0 = make_float4(acc[i][0], acc[i][1], acc[i][2], acc[i][3]);
            float4 s1 = make_float4(acc[i][4], acc[i][5], acc[i][6], acc[i][7]);
            *(float4*)(&g_gated[(size_t)e * COUT + tc * 8])     = s0;
            *(float4*)(&g_gated[(size_t)e * COUT + tc * 8 + 4]) = s1;
        }
    }

    float* Rs = Tsm;                  // [COUT][16]
    float* Rq = Tsm + COUT * 16;      // [COUT][16]
    #pragma unroll
    for (int j = 0; j < 8; ++j) {
        Rs[(tc * 8 + j) * 16 + te] = psum[j];
        Rq[(tc * 8 + j) * 16 + te] = psq[j];
    }
    __syncthreads();
    if (threadIdx.x < COUT) {
        int c = threadIdx.x;
        float s = 0.f;
        #pragma unroll
        for (int t = 0; t < 16; ++t) s += Rs[c * 16 + t];
        atomicAdd(&g_bn1_acc[c], s);
    } else {
        int c = threadIdx.x - COUT;
        float s = 0.f;
        #pragma unroll
        for (int t = 0; t < 16; ++t) s += Rq[c * 16 + t];
        atomicAdd(&g_bn1_acc[COUT + c], s);
    }
}

// ---------------- finalize BN1 ----------------
__global__ void finalize_bn1(const float* __restrict__ gg, const float* __restrict__ bb) {
    int c = threadIdx.x;  // 128
    const float invn = 1.f / (float)N_EDGES;
    float mu  = g_bn1_acc[c] * invn;
    float var = g_bn1_acc[COUT + c] * invn - mu * mu;
    float sc  = gg[c] * rsqrtf(var + EPSV);
    g_bn1_scale[c] = sc;
    g_bn1_shift[c] = bb[c] - mu * sc;
}

// ---------------- Kernel B2: normalize, gate, scatter-add ----------------
__global__ void msg_scatter_kernel(const int* __restrict__ ei) {
    long long id = (long long)blockIdx.x * blockDim.x + threadIdx.x;  // 64M total
    int c = (int)(id & 63);
    long long e = id >> 6;
    if (e >= N_EDGES) return;
    float nf = g_gated[e * COUT + c]        * g_bn1_scale[c]        + g_bn1_shift[c];
    float nc = g_gated[e * COUT + ATOM + c] * g_bn1_scale[ATOM + c] + g_bn1_shift[ATOM + c];
    float sg = 1.f / (1.f + expf(-nf));
    float sp = (nc > 20.f) ? nc : log1pf(expf(nc));
    atomicAdd(&g_summed[(size_t)ei[e] * ATOM + c], sg * sp);
}

// ---------------- Kernel C: BN2 stats over summed ----------------
__global__ void bn2_stats_kernel() {
    __shared__ float ss[ATOM], sq[ATOM];
    if (threadIdx.x < ATOM) { ss[threadIdx.x] = 0.f; sq[threadIdx.x] = 0.f; }
    __syncthreads();
    int c = threadIdx.x & 63;
    float ls = 0.f, lq = 0.f;
    long long stride = (long long)gridDim.x * blockDim.x;  // multiple of 64
    for (long long i = (long long)blockIdx.x * blockDim.x + threadIdx.x;
         i < (long long)N_NODES * ATOM; i += stride) {
        float v = g_summed[i];
        ls += v; lq += v * v;
    }
    atomicAdd(&ss[c], ls);
    atomicAdd(&sq[c], lq);
    __syncthreads();
    if (threadIdx.x < ATOM) {
        atomicAdd(&g_bn2_acc[threadIdx.x], ss[threadIdx.x]);
        atomicAdd(&g_bn2_acc[ATOM + threadIdx.x], sq[threadIdx.x]);
    }
}

__global__ void finalize_bn2(const float* __restrict__ gg, const float* __restrict__ bb) {
    int c = threadIdx.x;  // 64
    const float invn = 1.f / (float)N_NODES;
    float mu  = g_bn2_acc[c] * invn;
    float var = g_bn2_acc[ATOM + c] * invn - mu * mu;
    float sc  = gg[c] * rsqrtf(var + EPSV);
    g_bn2_scale[c] = sc;
    g_bn2_shift[c] = bb[c] - mu * sc;
}

// ---------------- Kernel D: atom_out (output!), h = silu, logits ----------------
__global__ void node_kernel(const float* __restrict__ attW,
                            const float* __restrict__ attb,
                            float* __restrict__ out) {
    int n = blockIdx.x;
    int c = threadIdx.x;  // 64
    float v = g_summed[(size_t)n * ATOM + c] * g_bn2_scale[c] + g_bn2_shift[c];
    out[(size_t)n * ATOM + c] = v;                     // atom_out output
    float hv = v / (1.f + expf(-v));                   // silu
    g_h[(size_t)n * ATOM + c] = hv;
    float p = hv * attW[c];
    #pragma unroll
    for (int o = 16; o > 0; o >>= 1) p += __shfl_down_sync(0xffffffff, p, o);
    __shared__ float r[2];
    if ((threadIdx.x & 31) == 0) r[threadIdx.x >> 5] = p;
    __syncthreads();
    if (threadIdx.x == 0) g_logits[n] = r[0] + r[1] + attb[0];
}

// ---------------- Kernel F: per-graph softmax attention pool ----------------
__device__ __forceinline__ int lbound(const int* a, int n, int key) {
    int lo = 0, hi = n;
    while (lo < hi) { int mid = (lo + hi) >> 1; if (a[mid] < key) lo = mid + 1; else hi = mid; }
    return lo;
}

__global__ void graph_kernel(const int* __restrict__ batch,
                             const float* __restrict__ outW,
                             const float* __restrict__ outb,
                             float* __restrict__ outp) {
    int g = blockIdx.x;
    __shared__ int s_lo, s_hi;
    __shared__ float red[256];
    __shared__ float s_max, s_den, s_rr[2];
    if (threadIdx.x == 0) {
        s_lo = lbound(batch, N_NODES, g);
        s_hi = lbound(batch, N_NODES, g + 1);
    }
    __syncthreads();
    int lo = s_lo, hi = s_hi;
    if (lo >= hi) {
        if (threadIdx.x == 0) outp[g] = outb[0];
        return;
    }
    // max logit
    float m = -INFINITY;
    for (int i = lo + threadIdx.x; i < hi; i += 256) m = fmaxf(m, g_logits[i]);
    red[threadIdx.x] = m;
    __syncthreads();
    for (int s = 128; s > 0; s >>= 1) {
        if (threadIdx.x < s) red[threadIdx.x] = fmaxf(red[threadIdx.x], red[threadIdx.x + s]);
        __syncthreads();
    }
    if (threadIdx.x == 0) s_max = red[0];
    __syncthreads();
    float mx = s_max;
    __syncthreads();
    // denom
    float se = 0.f;
    for (int i = lo + threadIdx.x; i < hi; i += 256) se += expf(g_logits[i] - mx);
    red[threadIdx.x] = se;
    __syncthreads();
    for (int s = 128; s > 0; s >>= 1) {
        if (threadIdx.x < s) red[threadIdx.x] += red[threadIdx.x + s];
        __syncthreads();
    }
    if (threadIdx.x == 0) s_den = red[0];
    __syncthreads();
    float denom = s_den;
    __syncthreads();
    // weighted feature sum
    int q = threadIdx.x >> 6;   // 0..3
    int c = threadIdx.x & 63;
    float a = 0.f;
    for (int i = lo + q; i < hi; i += 4)
        a += expf(g_logits[i] - mx) * g_h[(size_t)i * ATOM + c];
    red[threadIdx.x] = a;
    __syncthreads();
    if (threadIdx.x < ATOM) {
        float crys = (red[c] + red[64 + c] + red[128 + c] + red[192 + c]) / denom;
        float p = crys * outW[c];
        #pragma unroll
        for (int o = 16; o > 0; o >>= 1) p += __shfl_down_sync(0xffffffff, p, o);
        if ((threadIdx.x & 31) == 0) s_rr[threadIdx.x >> 5] = p;
    }
    __syncthreads();
    if (threadIdx.x == 0) outp[g] = s_rr[0] + s_rr[1] + outb[0];
}

// ---------------- host launcher ----------------
extern "C" void kernel_launch(void* const* d_in, const int* in_sizes, int n_in,
                              void* d_out, int out_size) {
    const float *x, *edge_attr, *lower_f, *embW, *embb, *fcW, *fcb;
    const float *bn1g, *bn1b, *bn2g, *bn2b, *attW, *attb, *outW, *outb;
    const int *ei, *batch;

    if (in_sizes[3] == 2 * N_EDGES) {
        // setup_inputs dict order
        x        = (const float*)d_in[0];
        edge_attr= (const float*)d_in[1];
        lower_f  = (const float*)d_in[2];
        ei       = (const int*)  d_in[3];
        batch    = (const int*)  d_in[4];
        embW     = (const float*)d_in[5];
        embb     = (const float*)d_in[6];
        fcW      = (const float*)d_in[7];
        fcb      = (const float*)d_in[8];
        bn1g     = (const float*)d_in[9];
        bn1b     = (const float*)d_in[10];
        bn2g     = (const float*)d_in[11];
        bn2b     = (const float*)d_in[12];
        attW     = (const float*)d_in[13];
        attb     = (const float*)d_in[14];
        outW     = (const float*)d_in[15];
        outb     = (const float*)d_in[16];
    } else {
        // reference() signature order
        x        = (const float*)d_in[0];
        edge_attr= (const float*)d_in[1];
        lower_f  = (const float*)d_in[2];
        embW     = (const float*)d_in[3];
        embb     = (const float*)d_in[4];
        fcW      = (const float*)d_in[5];
        fcb      = (const float*)d_in[6];
        bn1g     = (const float*)d_in[7];
        bn1b     = (const float*)d_in[8];
        bn2g     = (const float*)d_in[9];
        bn2b     = (const float*)d_in[10];
        attW     = (const float*)d_in[11];
        attb     = (const float*)d_in[12];
        outW     = (const float*)d_in[13];
        outb     = (const float*)d_in[14];
        ei       = (const int*)  d_in[15];
        batch    = (const int*)  d_in[16];
    }

    float* out = (float*)d_out;

    void *p_summed = nullptr, *p_bn1 = nullptr, *p_bn2 = nullptr;
    cudaGetSymbolAddress(&p_summed, g_summed);
    cudaGetSymbolAddress(&p_bn1, g_bn1_acc);
    cudaGetSymbolAddress(&p_bn2, g_bn2_acc);
    cudaMemsetAsync(p_summed, 0, (size_t)N_NODES * ATOM * sizeof(float), 0);
    cudaMemsetAsync(p_bn1, 0, 2 * COUT * sizeof(float), 0);
    cudaMemsetAsync(p_bn2, 0, 2 * ATOM * sizeof(float), 0);

    // A: node embedding
    atomfea_kernel<<<(N_NODES + A_NPB - 1) / A_NPB, 256>>>(x, embW, embb, lower_f);

    // B1: edge GEMM + BN1 stats
    cudaFuncSetAttribute(edge_gemm_kernel, cudaFuncAttributeMaxDynamicSharedMemorySize, B1_SMEM);
    edge_gemm_kernel<<<(N_EDGES + BE - 1) / BE, 256, B1_SMEM>>>(edge_attr, ei, fcW, fcb);

    finalize_bn1<<<1, COUT>>>(bn1g, bn1b);

    // B2: message + scatter
    {
        long long total = (long long)N_EDGES * ATOM;  // 64M
        int blocks = (int)((total + 255) / 256);
        msg_scatter_kernel<<<blocks, 256>>>(ei);
    }

    // C: BN2 stats + finalize
    bn2_stats_kernel<<<512, 256>>>();
    finalize_bn2<<<1, ATOM>>>(bn2g, bn2b);

    // D: atom_out output + h + logits
    node_kernel<<<N_NODES, ATOM>>>(attW, attb, out);

    // F: per-graph attention pooling -> crys_fea at tail of output
    graph_kernel<<<N_GRAPHS, 256>>>(batch, outW, outb, out + (size_t)N_NODES * ATOM);
}

// round 11
// speedup vs baseline: 2.1644x; 2.1644x over previous
#include <cuda_runtime.h>
#include <cuda_bf16.h>
#include <math.h>
#include <stdint.h>

#define N_NODES 50000
#define N_EDGES 1000000
#define N_GRAPHS 256
#define ORIG 92
#define ATOM 64
#define NBR 41
#define KTOT (2*ATOM + NBR)   // 169
#define KPAD 176              // pad to 22 k-steps of 8; k=169 is bias row
#define COUT (2*ATOM)         // 128
#define EPSV 1e-5f
#define NTILES ((N_EDGES + 127) / 128)   // 7813

#define ASTR 180              // A smem row stride (floats)
#define BSTR 136              // B smem row stride (floats)
#define TSTR 132              // transpose smem row stride (floats)

// ---------------- scratch ----------------
__device__ float g_atom_fea[(size_t)N_NODES * ATOM];
__device__ float g_gatedT[(size_t)COUT * N_EDGES];   // TRANSPOSED [c][e]
__device__ float g_summed[(size_t)N_NODES * ATOM];
__device__ float g_h[(size_t)N_NODES * ATOM];
__device__ float g_logits[N_NODES];
__device__ float g_bn1_acc[2 * COUT];
__device__ float g_bn1_scale[COUT];
__device__ float g_bn1_shift[COUT];
__device__ float g_bn2_acc[2 * ATOM];
__device__ float g_bn2_scale[ATOM];
__device__ float g_bn2_shift[ATOM];

__device__ __forceinline__ float to_tf32(float x) {
    float r; asm("cvt.rna.tf32.f32 %0, %1;" : "=f"(r) : "f"(x)); return r;
}

__device__ __forceinline__ void mma_tf32(float& d0, float& d1, float& d2, float& d3,
                                         uint32_t a0, uint32_t a1, uint32_t a2, uint32_t a3,
                                         uint32_t b0, uint32_t b1) {
    asm volatile("mma.sync.aligned.m16n8k8.row.col.f32.tf32.tf32.f32 "
                 "{%0,%1,%2,%3}, {%4,%5,%6,%7}, {%8,%9}, {%0,%1,%2,%3};"
                 : "+f"(d0), "+f"(d1), "+f"(d2), "+f"(d3)
                 : "r"(a0), "r"(a1), "r"(a2), "r"(a3), "r"(b0), "r"(b1));
}

// ---------------- Kernel A: atom_fea = x @ emb_W + emb_b + lower_f ----------------
#define A_NPB 256
__global__ void atomfea_kernel(const float* __restrict__ x,
                               const float* __restrict__ embW,
                               const float* __restrict__ embb,
                               const float* __restrict__ lower) {
    __shared__ float Wsm[ORIG * ATOM];
    __shared__ float xrow[4][ORIG];
    for (int i = threadIdx.x; i < ORIG * ATOM; i += 256) Wsm[i] = embW[i];
    int c = threadIdx.x & 63;
    int q = threadIdx.x >> 6;
    float bias = embb[c];
    for (int it = 0; it < A_NPB / 4; ++it) {
        int nbase = blockIdx.x * A_NPB + it * 4;
        __syncthreads();
        for (int i = threadIdx.x; i < 4 * ORIG; i += 256) {
            int nn = nbase + i / ORIG;
            xrow[i / ORIG][i % ORIG] = (nn < N_NODES) ? x[(size_t)nn * ORIG + (i % ORIG)] : 0.f;
        }
        __syncthreads();
        int n = nbase + q;
        if (n < N_NODES) {
            float s = bias;
            #pragma unroll 4
            for (int k = 0; k < ORIG; ++k) s = fmaf(xrow[q][k], Wsm[k * ATOM + c], s);
            g_atom_fea[(size_t)n * ATOM + c] = s + lower[(size_t)n * ATOM + c];
        }
    }
}

// ---------------- Kernel B1: edge GEMM via mma.sync tf32 + fused BN1 stats ----------------
// SMEM: As[128][ASTR] | Bs[KPAD][BSTR] | src[128] | dst[128]
#define SM_FLOATS (128*ASTR + KPAD*BSTR + 256)
#define SM_BYTES  (SM_FLOATS * 4)

__global__ void __launch_bounds__(256, 1)
edge_gemm_mma(const float* __restrict__ edge_attr,
              const int* __restrict__ ei,
              const float* __restrict__ fcW,
              const float* __restrict__ fcb) {
    extern __shared__ float sm[];
    float* As = sm;                       // [128][ASTR]
    float* Bs = sm + 128 * ASTR;          // [KPAD][BSTR]
    int*   s_src = (int*)(sm + 128 * ASTR + KPAD * BSTR);
    int*   s_dst = s_src + 128;

    const int tid  = threadIdx.x;
    const int wid  = tid >> 5;
    const int lane = tid & 31;
    const int g    = lane >> 2;     // 0..7
    const int t    = lane & 3;      // 0..3
    const int wm   = wid & 3;       // M group (32 rows)
    const int wn   = wid >> 2;      // N group (64 cols)

    const int e0 = blockIdx.x * 128;
    const int nvalid = min(128, N_EDGES - e0);

    // --- load B = fc_W [k][n], tf32-rounded; k==169 -> bias; k>169 -> 0 ---
    for (int i = tid; i < KPAD * COUT; i += 256) {
        int k = i >> 7, n = i & 127;
        float v = 0.f;
        if (k < KTOT)       v = fcW[(size_t)k * COUT + n];
        else if (k == KTOT) v = fcb[n];
        Bs[k * BSTR + n] = to_tf32(v);
    }

    // --- load edge indices ---
    if (tid < 128) {
        int e = e0 + tid;
        s_src[tid] = (e < N_EDGES) ? ei[e] : 0;
        s_dst[tid] = (e < N_EDGES) ? ei[N_EDGES + e] : 0;
    }
    __syncthreads();

    // --- gather A tile [128][176] tf32 ---
    for (int i = tid; i < 128 * 44; i += 256) {
        int m = i / 44, kg = i - (i / 44) * 44;
        float4 v = make_float4(0.f, 0.f, 0.f, 0.f);
        if (m < nvalid) {
            if (kg < 32) {
                int row = (kg < 16) ? s_src[m] : s_dst[m];
                v = *(const float4*)&g_atom_fea[(size_t)row * ATOM + (kg & 15) * 4];
            } else {
                int e = e0 + m;
                float tt[4];
                #pragma unroll
                for (int j = 0; j < 4; ++j) {
                    int k = kg * 4 + j;   // 128..175
                    tt[j] = (k < KTOT) ? edge_attr[(size_t)e * NBR + (k - COUT)]
                                       : (k == KTOT ? 1.0f : 0.f);
                }
                v = make_float4(tt[0], tt[1], tt[2], tt[3]);
            }
        }
        v.x = to_tf32(v.x); v.y = to_tf32(v.y); v.z = to_tf32(v.z); v.w = to_tf32(v.w);
        *(float4*)(As + m * ASTR + kg * 4) = v;
    }
    __syncthreads();

    // --- MMA mainloop: 22 k-steps ---
    float acc[2][8][4];
    #pragma unroll
    for (int mi = 0; mi < 2; ++mi)
        #pragma unroll
        for (int ni = 0; ni < 8; ++ni)
            #pragma unroll
            for (int r = 0; r < 4; ++r) acc[mi][ni][r] = 0.f;

    for (int ks = 0; ks < KPAD / 8; ++ks) {
        int k0 = ks * 8;
        uint32_t a[2][4], b[8][2];
        #pragma unroll
        for (int mi = 0; mi < 2; ++mi) {
            const float* p = As + (wm * 32 + mi * 16 + g) * ASTR + k0 + t;
            a[mi][0] = __float_as_uint(p[0]);
            a[mi][1] = __float_as_uint(p[8 * ASTR]);
            a[mi][2] = __float_as_uint(p[4]);
            a[mi][3] = __float_as_uint(p[8 * ASTR + 4]);
        }
        #pragma unroll
        for (int ni = 0; ni < 8; ++ni) {
            const float* p = Bs + (k0 + t) * BSTR + wn * 64 + ni * 8 + g;
            b[ni][0] = __float_as_uint(p[0]);
            b[ni][1] = __float_as_uint(p[4 * BSTR]);
        }
        #pragma unroll
        for (int mi = 0; mi < 2; ++mi)
            #pragma unroll
            for (int ni = 0; ni < 8; ++ni)
                mma_tf32(acc[mi][ni][0], acc[mi][ni][1], acc[mi][ni][2], acc[mi][ni][3],
                         a[mi][0], a[mi][1], a[mi][2], a[mi][3],
                         b[ni][0], b[ni][1]);
    }
    __syncthreads();   // done reading As; reuse as transpose buffer

    // --- transpose accums through SMEM: T[n][m], stride TSTR ---
    float* T = As;
    #pragma unroll
    for (int mi = 0; mi < 2; ++mi) {
        #pragma unroll
        for (int ni = 0; ni < 8; ++ni) {
            int m = wm * 32 + mi * 16 + g;
            int n = wn * 64 + ni * 8 + 2 * t;
            T[n * TSTR + m]           = acc[mi][ni][0];
            T[(n + 1) * TSTR + m]     = acc[mi][ni][1];
            T[n * TSTR + m + 8]       = acc[mi][ni][2];
            T[(n + 1) * TSTR + m + 8] = acc[mi][ni][3];
        }
    }
    __syncthreads();

    // --- coalesced store rows + fused BN1 stats ---
    #pragma unroll 4
    for (int rr = 0; rr < 16; ++rr) {
        int n = wid * 16 + rr;
        float4 v = *(float4*)&T[n * TSTR + lane * 4];
        if (lane * 4 < nvalid)
            *(float4*)&g_gatedT[(size_t)n * N_EDGES + e0 + lane * 4] = v;
        float s = v.x + v.y + v.z + v.w;
        float q = v.x * v.x + v.y * v.y + v.z * v.z + v.w * v.w;
        #pragma unroll
        for (int o = 16; o > 0; o >>= 1) {
            s += __shfl_down_sync(0xffffffff, s, o);
            q += __shfl_down_sync(0xffffffff, q, o);
        }
        if (lane == 0) {
            atomicAdd(&g_bn1_acc[n], s);
            atomicAdd(&g_bn1_acc[COUT + n], q);
        }
    }
}

// ---------------- finalize BN1 ----------------
__global__ void finalize_bn1(const float* __restrict__ gg, const float* __restrict__ bb) {
    int c = threadIdx.x;
    const float invn = 1.f / (float)N_EDGES;
    float mu  = g_bn1_acc[c] * invn;
    float var = g_bn1_acc[COUT + c] * invn - mu * mu;
    float sc  = gg[c] * rsqrtf(var + EPSV);
    g_bn1_scale[c] = sc;
    g_bn1_shift[c] = bb[c] - mu * sc;
}

// ---------------- msg + scatter (4 channels/thread, red.v4) ----------------
__global__ void msg_scatter_kernel(const int* __restrict__ ei) {
    int e = blockIdx.x * blockDim.x + threadIdx.x;
    if (e >= N_EDGES) return;
    int c = blockIdx.y * 4;
    float m[4];
    #pragma unroll
    for (int j = 0; j < 4; ++j) {
        float nf = g_gatedT[(size_t)(c + j) * N_EDGES + e]        * g_bn1_scale[c + j]        + g_bn1_shift[c + j];
        float nc = g_gatedT[(size_t)(c + j + ATOM) * N_EDGES + e] * g_bn1_scale[c + j + ATOM] + g_bn1_shift[c + j + ATOM];
        float sg = 1.f / (1.f + expf(-nf));
        float sp = (nc > 20.f) ? nc : log1pf(expf(nc));
        m[j] = sg * sp;
    }
    int src = ei[e];
    float* p = &g_summed[(size_t)src * ATOM + c];
    asm volatile("red.global.add.v4.f32 [%0], {%1, %2, %3, %4};"
                 :: "l"(p), "f"(m[0]), "f"(m[1]), "f"(m[2]), "f"(m[3]) : "memory");
}

// ---------------- BN2 ----------------
__global__ void bn2_stats_kernel() {
    __shared__ float ss[ATOM], sq[ATOM];
    if (threadIdx.x < ATOM) { ss[threadIdx.x] = 0.f; sq[threadIdx.x] = 0.f; }
    __syncthreads();
    int c = threadIdx.x & 63;
    float ls = 0.f, lq = 0.f;
    long long stride = (long long)gridDim.x * blockDim.x;
    for (long long i = (long long)blockIdx.x * blockDim.x + threadIdx.x;
         i < (long long)N_NODES * ATOM; i += stride) {
        float v = g_summed[i];
        ls += v; lq += v * v;
    }
    atomicAdd(&ss[c], ls);
    atomicAdd(&sq[c], lq);
    __syncthreads();
    if (threadIdx.x < ATOM) {
        atomicAdd(&g_bn2_acc[threadIdx.x], ss[threadIdx.x]);
        atomicAdd(&g_bn2_acc[ATOM + threadIdx.x], sq[threadIdx.x]);
    }
}

__global__ void finalize_bn2(const float* __restrict__ gg, const float* __restrict__ bb) {
    int c = threadIdx.x;
    const float invn = 1.f / (float)N_NODES;
    float mu  = g_bn2_acc[c] * invn;
    float var = g_bn2_acc[ATOM + c] * invn - mu * mu;
    float sc  = gg[c] * rsqrtf(var + EPSV);
    g_bn2_scale[c] = sc;
    g_bn2_shift[c] = bb[c] - mu * sc;
}

// ---------------- node stage ----------------
__global__ void node_kernel(const float* __restrict__ attW,
                            const float* __restrict__ attb,
                            float* __restrict__ out) {
    int n = blockIdx.x;
    int c = threadIdx.x;
    float v = g_summed[(size_t)n * ATOM + c] * g_bn2_scale[c] + g_bn2_shift[c];
    out[(size_t)n * ATOM + c] = v;
    float hv = v / (1.f + expf(-v));
    g_h[(size_t)n * ATOM + c] = hv;
    float p = hv * attW[c];
    #pragma unroll
    for (int o = 16; o > 0; o >>= 1) p += __shfl_down_sync(0xffffffff, p, o);
    __shared__ float r[2];
    if ((threadIdx.x & 31) == 0) r[threadIdx.x >> 5] = p;
    __syncthreads();
    if (threadIdx.x == 0) g_logits[n] = r[0] + r[1] + attb[0];
}

// ---------------- graph pooling ----------------
__device__ __forceinline__ int lbound(const int* a, int n, int key) {
    int lo = 0, hi = n;
    while (lo < hi) { int mid = (lo + hi) >> 1; if (a[mid] < key) lo = mid + 1; else hi = mid; }
    return lo;
}

__global__ void graph_kernel(const int* __restrict__ batch,
                             const float* __restrict__ outW,
                             const float* __restrict__ outb,
                             float* __restrict__ outp) {
    int g = blockIdx.x;
    __shared__ int s_lo, s_hi;
    __shared__ float red[256];
    __shared__ float s_max, s_den, s_rr[2];
    if (threadIdx.x == 0) {
        s_lo = lbound(batch, N_NODES, g);
        s_hi = lbound(batch, N_NODES, g + 1);
    }
    __syncthreads();
    int lo = s_lo, hi = s_hi;
    if (lo >= hi) {
        if (threadIdx.x == 0) outp[g] = outb[0];
        return;
    }
    float m = -INFINITY;
    for (int i = lo + threadIdx.x; i < hi; i += 256) m = fmaxf(m, g_logits[i]);
    red[threadIdx.x] = m;
    __syncthreads();
    for (int s = 128; s > 0; s >>= 1) {
        if (threadIdx.x < s) red[threadIdx.x] = fmaxf(red[threadIdx.x], red[threadIdx.x + s]);
        __syncthreads();
    }
    if (threadIdx.x == 0) s_max = red[0];
    __syncthreads();
    float mx = s_max;
    __syncthreads();
    float se = 0.f;
    for (int i = lo + threadIdx.x; i < hi; i += 256) se += expf(g_logits[i] - mx);
    red[threadIdx.x] = se;
    __syncthreads();
    for (int s = 128; s > 0; s >>= 1) {
        if (threadIdx.x < s) red[threadIdx.x] += red[threadIdx.x + s];
        __syncthreads();
    }
    if (threadIdx.x == 0) s_den = red[0];
    __syncthreads();
    float denom = s_den;
    __syncthreads();
    int q = threadIdx.x >> 6;
    int c = threadIdx.x & 63;
    float a = 0.f;
    for (int i = lo + q; i < hi; i += 4)
        a += expf(g_logits[i] - mx) * g_h[(size_t)i * ATOM + c];
    red[threadIdx.x] = a;
    __syncthreads();
    if (threadIdx.x < ATOM) {
        float crys = (red[c] + red[64 + c] + red[128 + c] + red[192 + c]) / denom;
        float p = crys * outW[c];
        #pragma unroll
        for (int o = 16; o > 0; o >>= 1) p += __shfl_down_sync(0xffffffff, p, o);
        if ((threadIdx.x & 31) == 0) s_rr[threadIdx.x >> 5] = p;
    }
    __syncthreads();
    if (threadIdx.x == 0) outp[g] = s_rr[0] + s_rr[1] + outb[0];
}

// ---------------- host launcher ----------------
extern "C" void kernel_launch(void* const* d_in, const int* in_sizes, int n_in,
                              void* d_out, int out_size) {
    const float *x, *edge_attr, *lower_f, *embW, *embb, *fcW, *fcb;
    const float *bn1g, *bn1b, *bn2g, *bn2b, *attW, *attb, *outW, *outb;
    const int *ei, *batch;

    if (in_sizes[3] == 2 * N_EDGES) {
        x        = (const float*)d_in[0];
        edge_attr= (const float*)d_in[1];
        lower_f  = (const float*)d_in[2];
        ei       = (const int*)  d_in[3];
        batch    = (const int*)  d_in[4];
        embW     = (const float*)d_in[5];
        embb     = (const float*)d_in[6];
        fcW      = (const float*)d_in[7];
        fcb      = (const float*)d_in[8];
        bn1g     = (const float*)d_in[9];
        bn1b     = (const float*)d_in[10];
        bn2g     = (const float*)d_in[11];
        bn2b     = (const float*)d_in[12];
        attW     = (const float*)d_in[13];
        attb     = (const float*)d_in[14];
        outW     = (const float*)d_in[15];
        outb     = (const float*)d_in[16];
    } else {
        x        = (const float*)d_in[0];
        edge_attr= (const float*)d_in[1];
        lower_f  = (const float*)d_in[2];
        embW     = (const float*)d_in[3];
        embb     = (const float*)d_in[4];
        fcW      = (const float*)d_in[5];
        fcb      = (const float*)d_in[6];
        bn1g     = (const float*)d_in[7];
        bn1b     = (const float*)d_in[8];
        bn2g     = (const float*)d_in[9];
        bn2b     = (const float*)d_in[10];
        attW     = (const float*)d_in[11];
        attb     = (const float*)d_in[12];
        outW     = (const float*)d_in[13];
        outb     = (const float*)d_in[14];
        ei       = (const int*)  d_in[15];
        batch    = (const int*)  d_in[16];
    }

    float* out = (float*)d_out;

    void *p_summed = nullptr, *p_bn1 = nullptr, *p_bn2 = nullptr;
    cudaGetSymbolAddress(&p_summed, g_summed);
    cudaGetSymbolAddress(&p_bn1, g_bn1_acc);
    cudaGetSymbolAddress(&p_bn2, g_bn2_acc);
    cudaMemsetAsync(p_summed, 0, (size_t)N_NODES * ATOM * sizeof(float), 0);
    cudaMemsetAsync(p_bn1, 0, 2 * COUT * sizeof(float), 0);
    cudaMemsetAsync(p_bn2, 0, 2 * ATOM * sizeof(float), 0);

    // A: node embedding
    atomfea_kernel<<<(N_NODES + A_NPB - 1) / A_NPB, 256>>>(x, embW, embb, lower_f);

    // B1: tensor-core (mma.sync tf32) edge GEMM -> g_gatedT, fused BN1 stats
    cudaFuncSetAttribute(edge_gemm_mma, cudaFuncAttributeMaxDynamicSharedMemorySize, SM_BYTES);
    edge_gemm_mma<<<NTILES, 256, SM_BYTES>>>(edge_attr, ei, fcW, fcb);

    finalize_bn1<<<1, COUT>>>(bn1g, bn1b);

    // B2: message + scatter (v4 reductions)
    {
        dim3 grid((N_EDGES + 255) / 256, ATOM / 4);
        msg_scatter_kernel<<<grid, 256>>>(ei);
    }

    // BN2
    bn2_stats_kernel<<<512, 256>>>();
    finalize_bn2<<<1, ATOM>>>(bn2g, bn2b);

    // node stage -> atom_out output
    node_kernel<<<N_NODES, ATOM>>>(attW, attb, out);

    // graph pooling -> crys_fea
    graph_kernel<<<N_GRAPHS, 256>>>(batch, outW, outb, out + (size_t)N_NODES * ATOM);
}

// round 14
// speedup vs baseline: 4.6574x; 2.1518x over previous
#include <cuda_runtime.h>
#include <cuda_bf16.h>
#include <math.h>
#include <stdint.h>

#define N_NODES 50000
#define N_EDGES 1000000
#define N_GRAPHS 256
#define ORIG 92
#define ATOM 64
#define NBR 41
#define KTOT (2*ATOM + NBR)   // 169
#define KPAD 176              // 22 k-steps of 8; k=169 is bias row
#define COUT (2*ATOM)         // 128
#define EPSV 1e-5f
#define NTILES ((N_EDGES + 127) / 128)   // 7813
#define GRID 148

#define ASTR 180              // A smem row stride (floats) — conflict-free frag reads
#define TSTR 132              // transpose smem row stride (floats)

// ---------------- scratch ----------------
__device__ float g_atom_fea[(size_t)N_NODES * ATOM];
__device__ float g_gatedT[(size_t)COUT * N_EDGES];   // TRANSPOSED [c][e]
__device__ float g_summed[(size_t)N_NODES * ATOM];
__device__ float g_h[(size_t)N_NODES * ATOM];
__device__ float g_logits[N_NODES];
__device__ float g_bn1_acc[2 * COUT];
__device__ float g_bn1_scale[COUT];
__device__ float g_bn1_shift[COUT];
__device__ float g_bn2_acc[2 * ATOM];
__device__ float g_bn2_scale[ATOM];
__device__ float g_bn2_shift[ATOM];

__device__ __forceinline__ float to_tf32(float x) {
    float r; asm("cvt.rna.tf32.f32 %0, %1;" : "=f"(r) : "f"(x)); return r;
}
__device__ __forceinline__ uint32_t smem_u32(const void* p) {
    uint32_t a;
    asm("{ .reg .u64 t; cvta.to.shared.u64 t, %1; cvt.u32.u64 %0, t; }" : "=r"(a) : "l"(p));
    return a;
}
#define CP16(dst, src) asm volatile("cp.async.cg.shared.global [%0], [%1], 16;" :: "r"(dst), "l"(src))
#define CP4(dst, src)  asm volatile("cp.async.ca.shared.global [%0], [%1], 4;"  :: "r"(dst), "l"(src))
#define CP_COMMIT()    asm volatile("cp.async.commit_group;" ::: "memory")
#define CP_WAIT0()     asm volatile("cp.async.wait_group 0;" ::: "memory")

__device__ __forceinline__ void mma_tf32(float* d,
                                         uint32_t a0, uint32_t a1, uint32_t a2, uint32_t a3,
                                         uint32_t b0, uint32_t b1) {
    asm volatile("mma.sync.aligned.m16n8k8.row.col.f32.tf32.tf32.f32 "
                 "{%0,%1,%2,%3}, {%4,%5,%6,%7}, {%8,%9}, {%0,%1,%2,%3};"
                 : "+f"(d[0]), "+f"(d[1]), "+f"(d[2]), "+f"(d[3])
                 : "r"(a0), "r"(a1), "r"(a2), "r"(a3), "r"(b0), "r"(b1));
}

// ---------------- Kernel A: atom_fea = x @ emb_W + emb_b + lower_f ----------------
#define A_NPB 256
__global__ void atomfea_kernel(const float* __restrict__ x,
                               const float* __restrict__ embW,
                               const float* __restrict__ embb,
                               const float* __restrict__ lower) {
    __shared__ float Wsm[ORIG * ATOM];
    __shared__ float xrow[4][ORIG];
    for (int i = threadIdx.x; i < ORIG * ATOM; i += 256) Wsm[i] = embW[i];
    int c = threadIdx.x & 63;
    int q = threadIdx.x >> 6;
    float bias = embb[c];
    for (int it = 0; it < A_NPB / 4; ++it) {
        int nbase = blockIdx.x * A_NPB + it * 4;
        __syncthreads();
        for (int i = threadIdx.x; i < 4 * ORIG; i += 256) {
            int nn = nbase + i / ORIG;
            xrow[i / ORIG][i % ORIG] = (nn < N_NODES) ? x[(size_t)nn * ORIG + (i % ORIG)] : 0.f;
        }
        __syncthreads();
        int n = nbase + q;
        if (n < N_NODES) {
            float s = bias;
            #pragma unroll 4
            for (int k = 0; k < ORIG; ++k) s = fmaf(xrow[q][k], Wsm[k * ATOM + c], s);
            g_atom_fea[(size_t)n * ATOM + c] = s + lower[(size_t)n * ATOM + c];
        }
    }
}

// ---------------- persistent pipelined edge GEMM ----------------
// SMEM: A0[128][ASTR] | A1[128][ASTR] | ib0[256] | ib1[256]
#define SM_BYTES (2*128*ASTR*4 + 2*256*4)

__device__ __forceinline__ void issue_gather(int tile, float* As, const int* ib,
                                             const float* __restrict__ edge_attr, int tid) {
    uint32_t abase = smem_u32(As);
    int e0 = tile * 128;
    int nv = min(128, N_EDGES - e0);
    // atom features: warp per edge-pair rows, fully coalesced 16B
    #pragma unroll
    for (int it = 0; it < 16; ++it) {
        int i = tid + it * 256;
        int m = i >> 5, kg = i & 31;
        if (m < nv) {
            int row = (kg < 16) ? ib[m] : ib[128 + m];
            const float* src = g_atom_fea + (size_t)row * ATOM + (kg & 15) * 4;
            uint32_t dst = abase + (uint32_t)(m * ASTR + kg * 4) * 4u;
            CP16(dst, src);
        }
    }
    // edge attrs: 2 threads per edge, 4B each, k=128..168
    {
        int m = tid >> 1;
        if (m < nv) {
            int e = e0 + m;
            const float* src = edge_attr + (size_t)e * NBR;
            uint32_t dbase = abase + (uint32_t)(m * ASTR + 128) * 4u;
            if (tid & 1) {
                #pragma unroll
                for (int k = 20; k < 41; ++k) CP4(dbase + k * 4u, src + k);
            } else {
                #pragma unroll
                for (int k = 0; k < 20; ++k) CP4(dbase + k * 4u, src + k);
            }
        }
    }
}

__global__ void __launch_bounds__(256, 1)
edge_gemm_mma(const float* __restrict__ edge_attr,
              const int* __restrict__ ei,
              const float* __restrict__ fcW,
              const float* __restrict__ fcb) {
    extern __shared__ float sm[];
    float* A0 = sm;
    float* A1 = sm + 128 * ASTR;
    int* ib0 = (int*)(sm + 2 * 128 * ASTR);
    int* ib1 = ib0 + 256;

    const int tid = threadIdx.x, wid = tid >> 5, lane = tid & 31;
    const int g = lane >> 2, t = lane & 3;

    // ---- B fragments in registers (per warp: 16 output cols, all 176 k) ----
    uint32_t breg[22][2][2];
    #pragma unroll
    for (int ks = 0; ks < 22; ++ks)
        #pragma unroll
        for (int nt = 0; nt < 2; ++nt) {
            int n = wid * 16 + nt * 8 + g;
            int k1 = ks * 8 + t, k2 = k1 + 4;
            float f1 = (k1 < KTOT) ? fcW[(size_t)k1 * COUT + n] : (k1 == KTOT ? fcb[n] : 0.f);
            float f2 = (k2 < KTOT) ? fcW[(size_t)k2 * COUT + n] : (k2 == KTOT ? fcb[n] : 0.f);
            breg[ks][nt][0] = __float_as_uint(to_tf32(f1));
            breg[ks][nt][1] = __float_as_uint(to_tf32(f2));
        }

    // ---- const K columns (bias=1 at k=169, zeros 170..175), both buffers ----
    if (tid < 128) {
        #pragma unroll
        for (int b = 0; b < 2; ++b) {
            float* R = (b ? A1 : A0) + tid * ASTR;
            R[169] = 1.f;
            #pragma unroll
            for (int j = 170; j < 176; ++j) R[j] = 0.f;
        }
    }

    int tile = blockIdx.x;
    // prologue: indices tile0
    {
        int e = tile * 128 + (tid & 127);
        int v = 0;
        if (e < N_EDGES) v = (tid < 128) ? ei[e] : ei[N_EDGES + e];
        ib0[tid] = v;
    }
    __syncthreads();
    issue_gather(tile, A0, ib0, edge_attr, tid);
    CP_COMMIT();
    {   // indices tile0+GRID
        int t1 = tile + GRID;
        int e = t1 * 128 + (tid & 127);
        int v = 0;
        if (t1 < NTILES && e < N_EDGES) v = (tid < 128) ? ei[e] : ei[N_EDGES + e];
        ib1[tid] = v;
    }
    CP_WAIT0();
    __syncthreads();

    float* Ab[2] = {A0, A1};
    int*   Ib[2] = {ib0, ib1};
    int cur = 0;

    for (; tile < NTILES; tile += GRID) {
        int nxt = cur ^ 1;
        int tnext = tile + GRID;
        if (tnext < NTILES) issue_gather(tnext, Ab[nxt], Ib[nxt], edge_attr, tid);
        CP_COMMIT();

        // prefetch indices for tile+2*GRID into regs (hidden behind MMA)
        int idxpre = 0;
        {
            int t2 = tile + 2 * GRID;
            int e = t2 * 128 + (tid & 127);
            if (t2 < NTILES && e < N_EDGES) idxpre = (tid < 128) ? ei[e] : ei[N_EDGES + e];
        }

        // ---- MMA over A[cur]: warp = all 128 rows x its 16 cols ----
        const float* Ac = Ab[cur];
        float acc[8][2][4];
        #pragma unroll
        for (int mi = 0; mi < 8; ++mi)
            #pragma unroll
            for (int nt = 0; nt < 2; ++nt)
                #pragma unroll
                for (int r = 0; r < 4; ++r) acc[mi][nt][r] = 0.f;

        #pragma unroll
        for (int ks = 0; ks < 22; ++ks) {
            #pragma unroll
            for (int mi = 0; mi < 8; ++mi) {
                const float* p = Ac + (mi * 16 + g) * ASTR + ks * 8 + t;
                uint32_t a0 = __float_as_uint(p[0]);
                uint32_t a1 = __float_as_uint(p[8 * ASTR]);
                uint32_t a2 = __float_as_uint(p[4]);
                uint32_t a3 = __float_as_uint(p[8 * ASTR + 4]);
                mma_tf32(acc[mi][0], a0, a1, a2, a3, breg[ks][0][0], breg[ks][0][1]);
                mma_tf32(acc[mi][1], a0, a1, a2, a3, breg[ks][1][0], breg[ks][1][1]);
            }
        }
        __syncthreads();   // all warps done reading A[cur]

        // ---- transpose acc -> T (reuse A[cur]) ----
        float* T = Ab[cur];
        #pragma unroll
        for (int mi = 0; mi < 8; ++mi)
            #pragma unroll
            for (int nt = 0; nt < 2; ++nt) {
                int m = mi * 16 + g;
                int n = wid * 16 + nt * 8 + 2 * t;
                T[n * TSTR + m]           = acc[mi][nt][0];
                T[(n + 1) * TSTR + m]     = acc[mi][nt][1];
                T[n * TSTR + m + 8]       = acc[mi][nt][2];
                T[(n + 1) * TSTR + m + 8] = acc[mi][nt][3];
            }
        __syncthreads();

        // ---- coalesced store + BN1 stats ----
        int e0 = tile * 128;
        int nv = min(128, N_EDGES - e0);
        #pragma unroll 4
        for (int rr = 0; rr < 16; ++rr) {
            int n = wid * 16 + rr;
            float4 v = *(float4*)&T[n * TSTR + lane * 4];
            bool ok = (lane * 4 < nv);
            if (ok) *(float4*)&g_gatedT[(size_t)n * N_EDGES + e0 + lane * 4] = v;
            float s = ok ? (v.x + v.y + v.z + v.w) : 0.f;
            float q = ok ? (v.x * v.x + v.y * v.y + v.z * v.z + v.w * v.w) : 0.f;
            #pragma unroll
            for (int o = 16; o > 0; o >>= 1) {
                s += __shfl_down_sync(0xffffffff, s, o);
                q += __shfl_down_sync(0xffffffff, q, o);
            }
            if (lane == 0) {
                atomicAdd(&g_bn1_acc[n], s);
                atomicAdd(&g_bn1_acc[COUT + n], q);
            }
        }
        __syncthreads();   // done reading T

        // re-init const K columns of A[cur]; stash prefetched indices
        if (tid < 128) {
            float* R = Ab[cur] + tid * ASTR;
            R[169] = 1.f;
            #pragma unroll
            for (int j = 170; j < 176; ++j) R[j] = 0.f;
        }
        Ib[cur][tid] = idxpre;

        CP_WAIT0();
        __syncthreads();
        cur = nxt;
    }
}

// ---------------- finalize BN1 ----------------
__global__ void finalize_bn1(const float* __restrict__ gg, const float* __restrict__ bb) {
    int c = threadIdx.x;
    const float invn = 1.f / (float)N_EDGES;
    float mu  = g_bn1_acc[c] * invn;
    float var = g_bn1_acc[COUT + c] * invn - mu * mu;
    float sc  = gg[c] * rsqrtf(var + EPSV);
    g_bn1_scale[c] = sc;
    g_bn1_shift[c] = bb[c] - mu * sc;
}

// ---------------- msg + scatter (4 channels/thread, red.v4) ----------------
__global__ void msg_scatter_kernel(const int* __restrict__ ei) {
    int e = blockIdx.x * blockDim.x + threadIdx.x;
    if (e >= N_EDGES) return;
    int c = blockIdx.y * 4;
    float m[4];
    #pragma unroll
    for (int j = 0; j < 4; ++j) {
        float nf = g_gatedT[(size_t)(c + j) * N_EDGES + e]        * g_bn1_scale[c + j]        + g_bn1_shift[c + j];
        float nc = g_gatedT[(size_t)(c + j + ATOM) * N_EDGES + e] * g_bn1_scale[c + j + ATOM] + g_bn1_shift[c + j + ATOM];
        float sg = 1.f / (1.f + expf(-nf));
        float sp = (nc > 20.f) ? nc : log1pf(expf(nc));
        m[j] = sg * sp;
    }
    int src = ei[e];
    float* p = &g_summed[(size_t)src * ATOM + c];
    asm volatile("red.global.add.v4.f32 [%0], {%1, %2, %3, %4};"
                 :: "l"(p), "f"(m[0]), "f"(m[1]), "f"(m[2]), "f"(m[3]) : "memory");
}

// ---------------- BN2 ----------------
__global__ void bn2_stats_kernel() {
    __shared__ float ss[ATOM], sq[ATOM];
    if (threadIdx.x < ATOM) { ss[threadIdx.x] = 0.f; sq[threadIdx.x] = 0.f; }
    __syncthreads();
    int c = threadIdx.x & 63;
    float ls = 0.f, lq = 0.f;
    long long stride = (long long)gridDim.x * blockDim.x;
    for (long long i = (long long)blockIdx.x * blockDim.x + threadIdx.x;
         i < (long long)N_NODES * ATOM; i += stride) {
        float v = g_summed[i];
        ls += v; lq += v * v;
    }
    atomicAdd(&ss[c], ls);
    atomicAdd(&sq[c], lq);
    __syncthreads();
    if (threadIdx.x < ATOM) {
        atomicAdd(&g_bn2_acc[threadIdx.x], ss[threadIdx.x]);
        atomicAdd(&g_bn2_acc[ATOM + threadIdx.x], sq[threadIdx.x]);
    }
}

__global__ void finalize_bn2(const float* __restrict__ gg, const float* __restrict__ bb) {
    int c = threadIdx.x;
    const float invn = 1.f / (float)N_NODES;
    float mu  = g_bn2_acc[c] * invn;
    float var = g_bn2_acc[ATOM + c] * invn - mu * mu;
    float sc  = gg[c] * rsqrtf(var + EPSV);
    g_bn2_scale[c] = sc;
    g_bn2_shift[c] = bb[c] - mu * sc;
}

// ---------------- node stage ----------------
__global__ void node_kernel(const float* __restrict__ attW,
                            const float* __restrict__ attb,
                            float* __restrict__ out) {
    int n = blockIdx.x;
    int c = threadIdx.x;
    float v = g_summed[(size_t)n * ATOM + c] * g_bn2_scale[c] + g_bn2_shift[c];
    out[(size_t)n * ATOM + c] = v;
    float hv = v / (1.f + expf(-v));
    g_h[(size_t)n * ATOM + c] = hv;
    float p = hv * attW[c];
    #pragma unroll
    for (int o = 16; o > 0; o >>= 1) p += __shfl_down_sync(0xffffffff, p, o);
    __shared__ float r[2];
    if ((threadIdx.x & 31) == 0) r[threadIdx.x >> 5] = p;
    __syncthreads();
    if (threadIdx.x == 0) g_logits[n] = r[0] + r[1] + attb[0];
}

// ---------------- graph pooling ----------------
__device__ __forceinline__ int lbound(const int* a, int n, int key) {
    int lo = 0, hi = n;
    while (lo < hi) { int mid = (lo + hi) >> 1; if (a[mid] < key) lo = mid + 1; else hi = mid; }
    return lo;
}

__global__ void graph_kernel(const int* __restrict__ batch,
                             const float* __restrict__ outW,
                             const float* __restrict__ outb,
                             float* __restrict__ outp) {
    int g = blockIdx.x;
    __shared__ int s_lo, s_hi;
    __shared__ float red[256];
    __shared__ float s_max, s_den, s_rr[2];
    if (threadIdx.x == 0) {
        s_lo = lbound(batch, N_NODES, g);
        s_hi = lbound(batch, N_NODES, g + 1);
    }
    __syncthreads();
    int lo = s_lo, hi = s_hi;
    if (lo >= hi) {
        if (threadIdx.x == 0) outp[g] = outb[0];
        return;
    }
    float m = -INFINITY;
    for (int i = lo + threadIdx.x; i < hi; i += 256) m = fmaxf(m, g_logits[i]);
    red[threadIdx.x] = m;
    __syncthreads();
    for (int s = 128; s > 0; s >>= 1) {
        if (threadIdx.x < s) red[threadIdx.x] = fmaxf(red[threadIdx.x], red[threadIdx.x + s]);
        __syncthreads();
    }
    if (threadIdx.x == 0) s_max = red[0];
    __syncthreads();
    float mx = s_max;
    __syncthreads();
    float se = 0.f;
    for (int i = lo + threadIdx.x; i < hi; i += 256) se += expf(g_logits[i] - mx);
    red[threadIdx.x] = se;
    __syncthreads();
    for (int s = 128; s > 0; s >>= 1) {
        if (threadIdx.x < s) red[threadIdx.x] += red[threadIdx.x + s];
        __syncthreads();
    }
    if (threadIdx.x == 0) s_den = red[0];
    __syncthreads();
    float denom = s_den;
    __syncthreads();
    int q = threadIdx.x >> 6;
    int c = threadIdx.x & 63;
    float a = 0.f;
    for (int i = lo + q; i < hi; i += 4)
        a += expf(g_logits[i] - mx) * g_h[(size_t)i * ATOM + c];
    red[threadIdx.x] = a;
    __syncthreads();
    if (threadIdx.x < ATOM) {
        float crys = (red[c] + red[64 + c] + red[128 + c] + red[192 + c]) / denom;
        float p = crys * outW[c];
        #pragma unroll
        for (int o = 16; o > 0; o >>= 1) p += __shfl_down_sync(0xffffffff, p, o);
        if ((threadIdx.x & 31) == 0) s_rr[threadIdx.x >> 5] = p;
    }
    __syncthreads();
    if (threadIdx.x == 0) outp[g] = s_rr[0] + s_rr[1] + outb[0];
}

// ---------------- host launcher ----------------
extern "C" void kernel_launch(void* const* d_in, const int* in_sizes, int n_in,
                              void* d_out, int out_size) {
    const float *x, *edge_attr, *lower_f, *embW, *embb, *fcW, *fcb;
    const float *bn1g, *bn1b, *bn2g, *bn2b, *attW, *attb, *outW, *outb;
    const int *ei, *batch;

    if (in_sizes[3] == 2 * N_EDGES) {
        x        = (const float*)d_in[0];
        edge_attr= (const float*)d_in[1];
        lower_f  = (const float*)d_in[2];
        ei       = (const int*)  d_in[3];
        batch    = (const int*)  d_in[4];
        embW     = (const float*)d_in[5];
        embb     = (const float*)d_in[6];
        fcW      = (const float*)d_in[7];
        fcb      = (const float*)d_in[8];
        bn1g     = (const float*)d_in[9];
        bn1b     = (const float*)d_in[10];
        bn2g     = (const float*)d_in[11];
        bn2b     = (const float*)d_in[12];
        attW     = (const float*)d_in[13];
        attb     = (const float*)d_in[14];
        outW     = (const float*)d_in[15];
        outb     = (const float*)d_in[16];
    } else {
        x        = (const float*)d_in[0];
        edge_attr= (const float*)d_in[1];
        lower_f  = (const float*)d_in[2];
        embW     = (const float*)d_in[3];
        embb     = (const float*)d_in[4];
        fcW      = (const float*)d_in[5];
        fcb      = (const float*)d_in[6];
        bn1g     = (const float*)d_in[7];
        bn1b     = (const float*)d_in[8];
        bn2g     = (const float*)d_in[9];
        bn2b     = (const float*)d_in[10];
        attW     = (const float*)d_in[11];
        attb     = (const float*)d_in[12];
        outW     = (const float*)d_in[13];
        outb     = (const float*)d_in[14];
        ei       = (const int*)  d_in[15];
        batch    = (const int*)  d_in[16];
    }

    float* out = (float*)d_out;

    void *p_summed = nullptr, *p_bn1 = nullptr, *p_bn2 = nullptr;
    cudaGetSymbolAddress(&p_summed, g_summed);
    cudaGetSymbolAddress(&p_bn1, g_bn1_acc);
    cudaGetSymbolAddress(&p_bn2, g_bn2_acc);
    cudaMemsetAsync(p_summed, 0, (size_t)N_NODES * ATOM * sizeof(float), 0);
    cudaMemsetAsync(p_bn1, 0, 2 * COUT * sizeof(float), 0);
    cudaMemsetAsync(p_bn2, 0, 2 * ATOM * sizeof(float), 0);

    // A: node embedding
    atomfea_kernel<<<(N_NODES + A_NPB - 1) / A_NPB, 256>>>(x, embW, embb, lower_f);

    // B1: persistent pipelined tensor-core edge GEMM -> g_gatedT (+ fused BN1 stats)
    cudaFuncSetAttribute(edge_gemm_mma, cudaFuncAttributeMaxDynamicSharedMemorySize, SM_BYTES);
    edge_gemm_mma<<<GRID, 256, SM_BYTES>>>(edge_attr, ei, fcW, fcb);

    finalize_bn1<<<1, COUT>>>(bn1g, bn1b);

    // B2: message + scatter (v4 reductions)
    {
        dim3 grid((N_EDGES + 255) / 256, ATOM / 4);
        msg_scatter_kernel<<<grid, 256>>>(ei);
    }

    // BN2
    bn2_stats_kernel<<<512, 256>>>();
    finalize_bn2<<<1, ATOM>>>(bn2g, bn2b);

    // node stage -> atom_out output
    node_kernel<<<N_NODES, ATOM>>>(attW, attb, out);

    // graph pooling -> crys_fea
    graph_kernel<<<N_GRAPHS, 256>>>(batch, outW, outb, out + (size_t)N_NODES * ATOM);
}

// round 15
// speedup vs baseline: 4.9134x; 1.0549x over previous
#include <cuda_runtime.h>
#include <cuda_bf16.h>
#include <math.h>
#include <stdint.h>

#define N_NODES 50000
#define N_EDGES 1000000
#define N_GRAPHS 256
#define ORIG 92
#define ATOM 64
#define NBR 41
#define KTOT (2*ATOM + NBR)   // 169
#define COUT (2*ATOM)         // 128
#define EPSV 1e-5f
#define NTILES ((N_EDGES + 127) / 128)   // 7813

#define EASTR 52              // edge_attr smem row stride (52 % 32 == 20 -> conflict-free frags)
#define SSTR 132              // Ssum / transpose smem row stride

// ---------------- scratch ----------------
__device__ float g_atom_fea[(size_t)N_NODES * ATOM];
__device__ float g_pcat[(size_t)N_NODES * 256];      // [i][0:128]=P1, [128:256]=P2 (51.2 MB)
__device__ float g_gatedT[(size_t)COUT * N_EDGES];   // TRANSPOSED [c][e]
__device__ float g_summed[(size_t)N_NODES * ATOM];
__device__ float g_h[(size_t)N_NODES * ATOM];
__device__ float g_logits[N_NODES];
__device__ float g_bn1_acc[2 * COUT];
__device__ float g_bn1_scale[COUT];
__device__ float g_bn1_shift[COUT];
__device__ float g_bn2_acc[2 * ATOM];
__device__ float g_bn2_scale[ATOM];
__device__ float g_bn2_shift[ATOM];

__device__ __forceinline__ float to_tf32(float x) {
    float r; asm("cvt.rna.tf32.f32 %0, %1;" : "=f"(r) : "f"(x)); return r;
}
__device__ __forceinline__ uint32_t smem_u32(const void* p) {
    uint32_t a;
    asm("{ .reg .u64 t; cvta.to.shared.u64 t, %1; cvt.u32.u64 %0, t; }" : "=r"(a) : "l"(p));
    return a;
}
#define CP4(dst, src)  asm volatile("cp.async.ca.shared.global [%0], [%1], 4;"  :: "r"(dst), "l"(src))
#define CP_COMMIT()    asm volatile("cp.async.commit_group;" ::: "memory")
#define CP_WAIT0()     asm volatile("cp.async.wait_group 0;" ::: "memory")

__device__ __forceinline__ void mma_tf32(float* d,
                                         uint32_t a0, uint32_t a1, uint32_t a2, uint32_t a3,
                                         uint32_t b0, uint32_t b1) {
    asm volatile("mma.sync.aligned.m16n8k8.row.col.f32.tf32.tf32.f32 "
                 "{%0,%1,%2,%3}, {%4,%5,%6,%7}, {%8,%9}, {%0,%1,%2,%3};"
                 : "+f"(d[0]), "+f"(d[1]), "+f"(d[2]), "+f"(d[3])
                 : "r"(a0), "r"(a1), "r"(a2), "r"(a3), "r"(b0), "r"(b1));
}

// ---------------- Kernel A: atom_fea = x @ emb_W + emb_b + lower_f ----------------
#define A_NPB 256
__global__ void atomfea_kernel(const float* __restrict__ x,
                               const float* __restrict__ embW,
                               const float* __restrict__ embb,
                               const float* __restrict__ lower) {
    __shared__ float Wsm[ORIG * ATOM];
    __shared__ float xrow[4][ORIG];
    for (int i = threadIdx.x; i < ORIG * ATOM; i += 256) Wsm[i] = embW[i];
    int c = threadIdx.x & 63;
    int q = threadIdx.x >> 6;
    float bias = embb[c];
    for (int it = 0; it < A_NPB / 4; ++it) {
        int nbase = blockIdx.x * A_NPB + it * 4;
        __syncthreads();
        for (int i = threadIdx.x; i < 4 * ORIG; i += 256) {
            int nn = nbase + i / ORIG;
            xrow[i / ORIG][i % ORIG] = (nn < N_NODES) ? x[(size_t)nn * ORIG + (i % ORIG)] : 0.f;
        }
        __syncthreads();
        int n = nbase + q;
        if (n < N_NODES) {
            float s = bias;
            #pragma unroll 4
            for (int k = 0; k < ORIG; ++k) s = fmaf(xrow[q][k], Wsm[k * ATOM + c], s);
            g_atom_fea[(size_t)n * ATOM + c] = s + lower[(size_t)n * ATOM + c];
        }
    }
}

// ---------------- Kernel P: Pcat = atom_fea @ [W1 | W2]  (K=64, N=256) ----------------
// Pcat[i][n] = sum_k atom_fea[i][k] * (n<128 ? fcW[k][n] : fcW[64+k][n-128])
#define P_NPB 128
#define P_SMEM ((64*256 + 2*64) * 4)
__global__ void pcat_kernel(const float* __restrict__ fcW) {
    extern __shared__ float psm[];
    float* Wsm = psm;                  // [64][256]
    float* arow = psm + 64 * 256;      // [2][64]
    int tid = threadIdx.x;
    for (int i = tid; i < 64 * 256; i += 256) {
        int k = i >> 8, n = i & 255;
        Wsm[i] = (n < 128) ? fcW[(size_t)k * COUT + n] : fcW[(size_t)(64 + k) * COUT + (n - 128)];
    }
    int c = tid;
    for (int it = 0; it < P_NPB / 2; ++it) {
        int n0 = blockIdx.x * P_NPB + it * 2;
        __syncthreads();
        if (tid < 128) {
            int nn = n0 + (tid >> 6);
            int k = tid & 63;
            arow[(tid >> 6) * 64 + k] = (nn < N_NODES) ? g_atom_fea[(size_t)nn * ATOM + k] : 0.f;
        }
        __syncthreads();
        float s0 = 0.f, s1 = 0.f;
        #pragma unroll 8
        for (int k = 0; k < 64; ++k) {
            float w = Wsm[k * 256 + c];
            s0 = fmaf(arow[k], w, s0);
            s1 = fmaf(arow[64 + k], w, s1);
        }
        if (n0 < N_NODES)     g_pcat[(size_t)n0 * 256 + c] = s0;
        if (n0 + 1 < N_NODES) g_pcat[(size_t)(n0 + 1) * 256 + c] = s1;
    }
}

// ---------------- Kernel B1: edge GEMM (K=41) + P-sum + fused BN1 stats ----------------
// SMEM: EA[128][EASTR] | SS[128][SSTR] | ib[256]
#define SM_FLOATS (128*EASTR + 128*SSTR + 256)
#define SM_BYTES  (SM_FLOATS * 4)   // 95232

__global__ void __launch_bounds__(256, 2)
edge_gemm_mma(const float* __restrict__ edge_attr,
              const int* __restrict__ ei,
              const float* __restrict__ fcW) {
    extern __shared__ float sm[];
    float* EA = sm;                              // [128][EASTR]
    float* SS = sm + 128 * EASTR;                // [128][SSTR]  (Ssum, then T)
    int*   ib = (int*)(sm + 128 * EASTR + 128 * SSTR);

    const int tid = threadIdx.x, wid = tid >> 5, lane = tid & 31;
    const int g = lane >> 2, t = lane & 3;

    // B fragments: W3 = fcW[128+k][n], k in [0,41), pad to 48 with zeros
    uint32_t breg[6][2][2];
    #pragma unroll
    for (int ks = 0; ks < 6; ++ks)
        #pragma unroll
        for (int nt = 0; nt < 2; ++nt) {
            int n = wid * 16 + nt * 8 + g;
            int k1 = ks * 8 + t, k2 = k1 + 4;
            float f1 = (k1 < NBR) ? fcW[(size_t)(COUT + k1) * COUT + n] : 0.f;
            float f2 = (k2 < NBR) ? fcW[(size_t)(COUT + k2) * COUT + n] : 0.f;
            breg[ks][nt][0] = __float_as_uint(to_tf32(f1));
            breg[ks][nt][1] = __float_as_uint(to_tf32(f2));
        }

    // const zero K-columns 41..47 of EA (persist across tiles; gather only writes 0..40)
    if (tid < 128) {
        #pragma unroll
        for (int j = NBR; j < 48; ++j) EA[tid * EASTR + j] = 0.f;
    }
    __syncthreads();

    for (int tile = blockIdx.x; tile < NTILES; tile += gridDim.x) {
        int e0 = tile * 128;
        int nv = min(128, N_EDGES - e0);

        // edge indices
        {
            int e = e0 + (tid & 127);
            int v = 0;
            if (e < N_EDGES) v = (tid < 128) ? ei[e] : ei[N_EDGES + e];
            ib[tid] = v;
        }

        // EA gather: 2 threads per edge, cp.async 4B
        {
            int m = tid >> 1;
            if (m < nv) {
                const float* src = edge_attr + (size_t)(e0 + m) * NBR;
                uint32_t db = smem_u32(EA + m * EASTR);
                if (tid & 1) {
                    #pragma unroll
                    for (int k = 20; k < NBR; ++k) CP4(db + k * 4u, src + k);
                } else {
                    #pragma unroll
                    for (int k = 0; k < 20; ++k) CP4(db + k * 4u, src + k);
                }
            }
        }
        CP_COMMIT();
        __syncthreads();   // ib visible to all

        // P-sum gather: SS[m][n] = P1[src[m]][n] + P2[dst[m]][n]  (coalesced rows)
        {
            int m0 = wid * 16;
            #pragma unroll 4
            for (int em = 0; em < 16; ++em) {
                int m = m0 + em;
                int s = ib[m], d = ib[128 + m];
                float4 p1 = *(const float4*)&g_pcat[(size_t)s * 256 + lane * 4];
                float4 p2 = *(const float4*)&g_pcat[(size_t)d * 256 + 128 + lane * 4];
                p1.x += p2.x; p1.y += p2.y; p1.z += p2.z; p1.w += p2.w;
                *(float4*)&SS[m * SSTR + lane * 4] = p1;
            }
        }
        CP_WAIT0();
        __syncthreads();   // EA + SS ready

        // MMA: 6 k-steps over edge_attr
        float acc[8][2][4];
        #pragma unroll
        for (int mi = 0; mi < 8; ++mi)
            #pragma unroll
            for (int nt = 0; nt < 2; ++nt)
                #pragma unroll
                for (int r = 0; r < 4; ++r) acc[mi][nt][r] = 0.f;

        #pragma unroll
        for (int ks = 0; ks < 6; ++ks) {
            #pragma unroll
            for (int mi = 0; mi < 8; ++mi) {
                const float* p = EA + (mi * 16 + g) * EASTR + ks * 8 + t;
                uint32_t a0 = __float_as_uint(p[0]);
                uint32_t a1 = __float_as_uint(p[8 * EASTR]);
                uint32_t a2 = __float_as_uint(p[4]);
                uint32_t a3 = __float_as_uint(p[8 * EASTR + 4]);
                mma_tf32(acc[mi][0], a0, a1, a2, a3, breg[ks][0][0], breg[ks][0][1]);
                mma_tf32(acc[mi][1], a0, a1, a2, a3, breg[ks][1][0], breg[ks][1][1]);
            }
        }

        // acc += Ssum  (C frag: rows g,g+8; cols 2t,2t+1)
        #pragma unroll
        for (int mi = 0; mi < 8; ++mi)
            #pragma unroll
            for (int nt = 0; nt < 2; ++nt) {
                int m = mi * 16 + g;
                int n0 = wid * 16 + nt * 8 + 2 * t;
                float2 u = *(float2*)&SS[m * SSTR + n0];
                float2 v = *(float2*)&SS[(m + 8) * SSTR + n0];
                acc[mi][nt][0] += u.x; acc[mi][nt][1] += u.y;
                acc[mi][nt][2] += v.x; acc[mi][nt][3] += v.y;
            }
        __syncthreads();   // all SS reads done -> reuse SS as transpose buffer

        // transpose acc -> SS as T[n][m]
        #pragma unroll
        for (int mi = 0; mi < 8; ++mi)
            #pragma unroll
            for (int nt = 0; nt < 2; ++nt) {
                int m = mi * 16 + g;
                int n = wid * 16 + nt * 8 + 2 * t;
                SS[n * SSTR + m]           = acc[mi][nt][0];
                SS[(n + 1) * SSTR + m]     = acc[mi][nt][1];
                SS[n * SSTR + m + 8]       = acc[mi][nt][2];
                SS[(n + 1) * SSTR + m + 8] = acc[mi][nt][3];
            }
        __syncthreads();

        // coalesced store + fused BN1 stats
        #pragma unroll 4
        for (int rr = 0; rr < 16; ++rr) {
            int n = wid * 16 + rr;
            float4 v = *(float4*)&SS[n * SSTR + lane * 4];
            bool ok = (lane * 4 < nv);
            if (ok) *(float4*)&g_gatedT[(size_t)n * N_EDGES + e0 + lane * 4] = v;
            float s = ok ? (v.x + v.y + v.z + v.w) : 0.f;
            float q = ok ? (v.x * v.x + v.y * v.y + v.z * v.z + v.w * v.w) : 0.f;
            #pragma unroll
            for (int o = 16; o > 0; o >>= 1) {
                s += __shfl_down_sync(0xffffffff, s, o);
                q += __shfl_down_sync(0xffffffff, q, o);
            }
            if (lane == 0) {
                atomicAdd(&g_bn1_acc[n], s);
                atomicAdd(&g_bn1_acc[COUT + n], q);
            }
        }
        __syncthreads();   // SS free for next iteration
    }
}

// ---------------- finalize BN1 ----------------
__global__ void finalize_bn1(const float* __restrict__ gg, const float* __restrict__ bb) {
    int c = threadIdx.x;
    const float invn = 1.f / (float)N_EDGES;
    float mu  = g_bn1_acc[c] * invn;
    float var = g_bn1_acc[COUT + c] * invn - mu * mu;
    float sc  = gg[c] * rsqrtf(var + EPSV);
    g_bn1_scale[c] = sc;
    g_bn1_shift[c] = bb[c] - mu * sc;
}

// ---------------- msg + scatter: 4 edges x 4 channels per thread ----------------
__global__ void msg_scatter_kernel(const int* __restrict__ ei) {
    int base = (blockIdx.x * blockDim.x + threadIdx.x) * 4;
    if (base >= N_EDGES) return;
    int c = blockIdx.y * 4;
    float4 F[4], C[4];
    #pragma unroll
    for (int j = 0; j < 4; ++j) {
        F[j] = *(const float4*)&g_gatedT[(size_t)(c + j) * N_EDGES + base];
        C[j] = *(const float4*)&g_gatedT[(size_t)(c + j + ATOM) * N_EDGES + base];
    }
    int srcs[4];
    #pragma unroll
    for (int ee = 0; ee < 4; ++ee) srcs[ee] = ei[base + ee];
    #pragma unroll
    for (int ee = 0; ee < 4; ++ee) {
        float m[4];
        #pragma unroll
        for (int j = 0; j < 4; ++j) {
            float gf = reinterpret_cast<const float*>(&F[j])[ee];
            float gc = reinterpret_cast<const float*>(&C[j])[ee];
            float nf = gf * g_bn1_scale[c + j]        + g_bn1_shift[c + j];
            float nc = gc * g_bn1_scale[c + j + ATOM] + g_bn1_shift[c + j + ATOM];
            float sg = 1.f / (1.f + expf(-nf));
            float sp = (nc > 20.f) ? nc : log1pf(expf(nc));
            m[j] = sg * sp;
        }
        float* p = &g_summed[(size_t)srcs[ee] * ATOM + c];
        asm volatile("red.global.add.v4.f32 [%0], {%1, %2, %3, %4};"
                     :: "l"(p), "f"(m[0]), "f"(m[1]), "f"(m[2]), "f"(m[3]) : "memory");
    }
}

// ---------------- BN2 ----------------
__global__ void bn2_stats_kernel() {
    __shared__ float ss[ATOM], sq[ATOM];
    if (threadIdx.x < ATOM) { ss[threadIdx.x] = 0.f; sq[threadIdx.x] = 0.f; }
    __syncthreads();
    int c = threadIdx.x & 63;
    float ls = 0.f, lq = 0.f;
    long long stride = (long long)gridDim.x * blockDim.x;
    for (long long i = (long long)blockIdx.x * blockDim.x + threadIdx.x;
         i < (long long)N_NODES * ATOM; i += stride) {
        float v = g_summed[i];
        ls += v; lq += v * v;
    }
    atomicAdd(&ss[c], ls);
    atomicAdd(&sq[c], lq);
    __syncthreads();
    if (threadIdx.x < ATOM) {
        atomicAdd(&g_bn2_acc[threadIdx.x], ss[threadIdx.x]);
        atomicAdd(&g_bn2_acc[ATOM + threadIdx.x], sq[threadIdx.x]);
    }
}

__global__ void finalize_bn2(const float* __restrict__ gg, const float* __restrict__ bb) {
    int c = threadIdx.x;
    const float invn = 1.f / (float)N_NODES;
    float mu  = g_bn2_acc[c] * invn;
    float var = g_bn2_acc[ATOM + c] * invn - mu * mu;
    float sc  = gg[c] * rsqrtf(var + EPSV);
    g_bn2_scale[c] = sc;
    g_bn2_shift[c] = bb[c] - mu * sc;
}

// ---------------- node stage ----------------
__global__ void node_kernel(const float* __restrict__ attW,
                            const float* __restrict__ attb,
                            float* __restrict__ out) {
    int n = blockIdx.x;
    int c = threadIdx.x;
    float v = g_summed[(size_t)n * ATOM + c] * g_bn2_scale[c] + g_bn2_shift[c];
    out[(size_t)n * ATOM + c] = v;
    float hv = v / (1.f + expf(-v));
    g_h[(size_t)n * ATOM + c] = hv;
    float p = hv * attW[c];
    #pragma unroll
    for (int o = 16; o > 0; o >>= 1) p += __shfl_down_sync(0xffffffff, p, o);
    __shared__ float r[2];
    if ((threadIdx.x & 31) == 0) r[threadIdx.x >> 5] = p;
    __syncthreads();
    if (threadIdx.x == 0) g_logits[n] = r[0] + r[1] + attb[0];
}

// ---------------- graph pooling ----------------
__device__ __forceinline__ int lbound(const int* a, int n, int key) {
    int lo = 0, hi = n;
    while (lo < hi) { int mid = (lo + hi) >> 1; if (a[mid] < key) lo = mid + 1; else hi = mid; }
    return lo;
}

__global__ void graph_kernel(const int* __restrict__ batch,
                             const float* __restrict__ outW,
                             const float* __restrict__ outb,
                             float* __restrict__ outp) {
    int g = blockIdx.x;
    __shared__ int s_lo, s_hi;
    __shared__ float red[256];
    __shared__ float s_max, s_den, s_rr[2];
    if (threadIdx.x == 0) {
        s_lo = lbound(batch, N_NODES, g);
        s_hi = lbound(batch, N_NODES, g + 1);
    }
    __syncthreads();
    int lo = s_lo, hi = s_hi;
    if (lo >= hi) {
        if (threadIdx.x == 0) outp[g] = outb[0];
        return;
    }
    float m = -INFINITY;
    for (int i = lo + threadIdx.x; i < hi; i += 256) m = fmaxf(m, g_logits[i]);
    red[threadIdx.x] = m;
    __syncthreads();
    for (int s = 128; s > 0; s >>= 1) {
        if (threadIdx.x < s) red[threadIdx.x] = fmaxf(red[threadIdx.x], red[threadIdx.x + s]);
        __syncthreads();
    }
    if (threadIdx.x == 0) s_max = red[0];
    __syncthreads();
    float mx = s_max;
    __syncthreads();
    float se = 0.f;
    for (int i = lo + threadIdx.x; i < hi; i += 256) se += expf(g_logits[i] - mx);
    red[threadIdx.x] = se;
    __syncthreads();
    for (int s = 128; s > 0; s >>= 1) {
        if (threadIdx.x < s) red[threadIdx.x] += red[threadIdx.x + s];
        __syncthreads();
    }
    if (threadIdx.x == 0) s_den = red[0];
    __syncthreads();
    float denom = s_den;
    __syncthreads();
    int q = threadIdx.x >> 6;
    int c = threadIdx.x & 63;
    float a = 0.f;
    for (int i = lo + q; i < hi; i += 4)
        a += expf(g_logits[i] - mx) * g_h[(size_t)i * ATOM + c];
    red[threadIdx.x] = a;
    __syncthreads();
    if (threadIdx.x < ATOM) {
        float crys = (red[c] + red[64 + c] + red[128 + c] + red[192 + c]) / denom;
        float p = crys * outW[c];
        #pragma unroll
        for (int o = 16; o > 0; o >>= 1) p += __shfl_down_sync(0xffffffff, p, o);
        if ((threadIdx.x & 31) == 0) s_rr[threadIdx.x >> 5] = p;
    }
    __syncthreads();
    if (threadIdx.x == 0) outp[g] = s_rr[0] + s_rr[1] + outb[0];
}

// ---------------- host launcher ----------------
extern "C" void kernel_launch(void* const* d_in, const int* in_sizes, int n_in,
                              void* d_out, int out_size) {
    const float *x, *edge_attr, *lower_f, *embW, *embb, *fcW, *fcb;
    const float *bn1g, *bn1b, *bn2g, *bn2b, *attW, *attb, *outW, *outb;
    const int *ei, *batch;

    if (in_sizes[3] == 2 * N_EDGES) {
        x        = (const float*)d_in[0];
        edge_attr= (const float*)d_in[1];
        lower_f  = (const float*)d_in[2];
        ei       = (const int*)  d_in[3];
        batch    = (const int*)  d_in[4];
        embW     = (const float*)d_in[5];
        embb     = (const float*)d_in[6];
        fcW      = (const float*)d_in[7];
        fcb      = (const float*)d_in[8];
        bn1g     = (const float*)d_in[9];
        bn1b     = (const float*)d_in[10];
        bn2g     = (const float*)d_in[11];
        bn2b     = (const float*)d_in[12];
        attW     = (const float*)d_in[13];
        attb     = (const float*)d_in[14];
        outW     = (const float*)d_in[15];
        outb     = (const float*)d_in[16];
    } else {
        x        = (const float*)d_in[0];
        edge_attr= (const float*)d_in[1];
        lower_f  = (const float*)d_in[2];
        embW     = (const float*)d_in[3];
        embb     = (const float*)d_in[4];
        fcW      = (const float*)d_in[5];
        fcb      = (const float*)d_in[6];
        bn1g     = (const float*)d_in[7];
        bn1b     = (const float*)d_in[8];
        bn2g     = (const float*)d_in[9];
        bn2b     = (const float*)d_in[10];
        attW     = (const float*)d_in[11];
        attb     = (const float*)d_in[12];
        outW     = (const float*)d_in[13];
        outb     = (const float*)d_in[14];
        ei       = (const int*)  d_in[15];
        batch    = (const int*)  d_in[16];
    }
    (void)fcb;  // fc bias cancels exactly through train-mode BN1

    float* out = (float*)d_out;

    void *p_summed = nullptr, *p_bn1 = nullptr, *p_bn2 = nullptr;
    cudaGetSymbolAddress(&p_summed, g_summed);
    cudaGetSymbolAddress(&p_bn1, g_bn1_acc);
    cudaGetSymbolAddress(&p_bn2, g_bn2_acc);
    cudaMemsetAsync(p_summed, 0, (size_t)N_NODES * ATOM * sizeof(float), 0);
    cudaMemsetAsync(p_bn1, 0, 2 * COUT * sizeof(float), 0);
    cudaMemsetAsync(p_bn2, 0, 2 * ATOM * sizeof(float), 0);

    // A: node embedding
    atomfea_kernel<<<(N_NODES + A_NPB - 1) / A_NPB, 256>>>(x, embW, embb, lower_f);

    // P: node-side partial products Pcat = atom_fea @ [W1|W2]
    cudaFuncSetAttribute(pcat_kernel, cudaFuncAttributeMaxDynamicSharedMemorySize, P_SMEM);
    pcat_kernel<<<(N_NODES + P_NPB - 1) / P_NPB, 256, P_SMEM>>>(fcW);

    // B1: edge GEMM (K=41) + P1[src]+P2[dst], fused BN1 stats; 2 CTAs/SM persistent
    cudaFuncSetAttribute(edge_gemm_mma, cudaFuncAttributeMaxDynamicSharedMemorySize, SM_BYTES);
    edge_gemm_mma<<<296, 256, SM_BYTES>>>(edge_attr, ei, fcW);

    finalize_bn1<<<1, COUT>>>(bn1g, bn1b);

    // B2: message + scatter (float4 loads, v4 reductions)
    {
        dim3 grid((N_EDGES / 4 + 255) / 256, ATOM / 4);
        msg_scatter_kernel<<<grid, 256>>>(ei);
    }

    // BN2
    bn2_stats_kernel<<<512, 256>>>();
    finalize_bn2<<<1, ATOM>>>(bn2g, bn2b);

    // node stage -> atom_out output
    node_kernel<<<N_NODES, ATOM>>>(attW, attb, out);

    // graph pooling -> crys_fea
    graph_kernel<<<N_GRAPHS, 256>>>(batch, outW, outb, out + (size_t)N_NODES * ATOM);
}

// round 17
// speedup vs baseline: 4.9717x; 1.0119x over previous
#include <cuda_runtime.h>
#include <cuda_bf16.h>
#include <math.h>
#include <stdint.h>

#define N_NODES 50000
#define N_EDGES 1000000
#define N_GRAPHS 256
#define ORIG 92
#define ATOM 64
#define NBR 41
#define COUT (2*ATOM)         // 128
#define EPSV 1e-5f
#define NTILES ((N_EDGES + 127) / 128)   // 7813
#define EGRID 296

#define EASTR 52              // edge_attr smem row stride (conflict-free frag reads)
#define SSTR 132              // transpose smem row stride

// ---------------- scratch ----------------
__device__ float g_atom_fea[(size_t)N_NODES * ATOM];
__device__ float g_pcat[(size_t)N_NODES * 256];      // [i][0:128]=P1, [128:256]=P2
__device__ float g_gatedT[(size_t)COUT * N_EDGES];   // TRANSPOSED [c][e]
__device__ float g_summed[(size_t)N_NODES * ATOM];
__device__ float g_h[(size_t)N_NODES * ATOM];
__device__ float g_logits[N_NODES];
__device__ float g_bn1_acc[2 * COUT];
__device__ float g_bn1_scale[COUT];
__device__ float g_bn1_shift[COUT];
__device__ float g_bn2_acc[2 * ATOM];
__device__ float g_bn2_scale[ATOM];
__device__ float g_bn2_shift[ATOM];

__device__ __forceinline__ float to_tf32(float x) {
    float r; asm("cvt.rna.tf32.f32 %0, %1;" : "=f"(r) : "f"(x)); return r;
}
__device__ __forceinline__ uint32_t smem_u32(const void* p) {
    uint32_t a;
    asm("{ .reg .u64 t; cvta.to.shared.u64 t, %1; cvt.u32.u64 %0, t; }" : "=r"(a) : "l"(p));
    return a;
}
#define CP4(dst, src)  asm volatile("cp.async.ca.shared.global [%0], [%1], 4;"  :: "r"(dst), "l"(src))
#define CP_COMMIT()    asm volatile("cp.async.commit_group;" ::: "memory")
#define CP_WAIT0()     asm volatile("cp.async.wait_group 0;" ::: "memory")

__device__ __forceinline__ void mma_tf32(float* d,
                                         uint32_t a0, uint32_t a1, uint32_t a2, uint32_t a3,
                                         uint32_t b0, uint32_t b1) {
    asm volatile("mma.sync.aligned.m16n8k8.row.col.f32.tf32.tf32.f32 "
                 "{%0,%1,%2,%3}, {%4,%5,%6,%7}, {%8,%9}, {%0,%1,%2,%3};"
                 : "+f"(d[0]), "+f"(d[1]), "+f"(d[2]), "+f"(d[3])
                 : "r"(a0), "r"(a1), "r"(a2), "r"(a3), "r"(b0), "r"(b1));
}

// ---------------- Kernel A: atom_fea = x @ emb_W + emb_b + lower_f ----------------
#define A_NPB 256
__global__ void atomfea_kernel(const float* __restrict__ x,
                               const float* __restrict__ embW,
                               const float* __restrict__ embb,
                               const float* __restrict__ lower) {
    __shared__ float Wsm[ORIG * ATOM];
    __shared__ float xrow[4][ORIG];
    for (int i = threadIdx.x; i < ORIG * ATOM; i += 256) Wsm[i] = embW[i];
    int c = threadIdx.x & 63;
    int q = threadIdx.x >> 6;
    float bias = embb[c];
    for (int it = 0; it < A_NPB / 4; ++it) {
        int nbase = blockIdx.x * A_NPB + it * 4;
        __syncthreads();
        for (int i = threadIdx.x; i < 4 * ORIG; i += 256) {
            int nn = nbase + i / ORIG;
            xrow[i / ORIG][i % ORIG] = (nn < N_NODES) ? x[(size_t)nn * ORIG + (i % ORIG)] : 0.f;
        }
        __syncthreads();
        int n = nbase + q;
        if (n < N_NODES) {
            float s = bias;
            #pragma unroll 4
            for (int k = 0; k < ORIG; ++k) s = fmaf(xrow[q][k], Wsm[k * ATOM + c], s);
            g_atom_fea[(size_t)n * ATOM + c] = s + lower[(size_t)n * ATOM + c];
        }
    }
}

// ---------------- Kernel P: Pcat = atom_fea @ [W1 | W2]  (K=64, N=256) ----------------
#define P_NPB 128
#define P_SMEM ((64*256 + 2*64) * 4)
__global__ void pcat_kernel(const float* __restrict__ fcW) {
    extern __shared__ float psm[];
    float* Wsm = psm;                  // [64][256]
    float* arow = psm + 64 * 256;      // [2][64]
    int tid = threadIdx.x;
    for (int i = tid; i < 64 * 256; i += 256) {
        int k = i >> 8, n = i & 255;
        Wsm[i] = (n < 128) ? fcW[(size_t)k * COUT + n] : fcW[(size_t)(64 + k) * COUT + (n - 128)];
    }
    int c = tid;
    for (int it = 0; it < P_NPB / 2; ++it) {
        int n0 = blockIdx.x * P_NPB + it * 2;
        __syncthreads();
        if (tid < 128) {
            int nn = n0 + (tid >> 6);
            int k = tid & 63;
            arow[(tid >> 6) * 64 + k] = (nn < N_NODES) ? g_atom_fea[(size_t)nn * ATOM + k] : 0.f;
        }
        __syncthreads();
        float s0 = 0.f, s1 = 0.f;
        #pragma unroll 8
        for (int k = 0; k < 64; ++k) {
            float w = Wsm[k * 256 + c];
            s0 = fmaf(arow[k], w, s0);
            s1 = fmaf(arow[64 + k], w, s1);
        }
        if (n0 < N_NODES)     g_pcat[(size_t)n0 * 256 + c] = s0;
        if (n0 + 1 < N_NODES) g_pcat[(size_t)(n0 + 1) * 256 + c] = s1;
    }
}

// ---------------- Kernel B1: edge GEMM (K=41), psum direct-to-acc, fused BN1 ----------------
// SMEM: EA[128][EASTR] | SS[128][SSTR] | ib[256]
#define SM_FLOATS (128*EASTR + 128*SSTR + 256)
#define SM_BYTES  (SM_FLOATS * 4)   // 95232 -> 2 CTAs/SM

__global__ void __launch_bounds__(256, 2)
edge_gemm_mma(const float* __restrict__ edge_attr,
              const int* __restrict__ ei,
              const float* __restrict__ fcW) {
    extern __shared__ float sm[];
    float* EA = sm;                              // [128][EASTR]
    float* SS = sm + 128 * EASTR;                // [128][SSTR]  (transpose buffer)
    int*   ib = (int*)(sm + 128 * EASTR + 128 * SSTR);

    const int tid = threadIdx.x, wid = tid >> 5, lane = tid & 31;
    const int g = lane >> 2, t = lane & 3;

    // B fragments: W3 = fcW[128+k][n], k in [0,41), pad to 48 with zeros
    uint32_t breg[6][2][2];
    #pragma unroll
    for (int ks = 0; ks < 6; ++ks)
        #pragma unroll
        for (int nt = 0; nt < 2; ++nt) {
            int n = wid * 16 + nt * 8 + g;
            int k1 = ks * 8 + t, k2 = k1 + 4;
            float f1 = (k1 < NBR) ? fcW[(size_t)(COUT + k1) * COUT + n] : 0.f;
            float f2 = (k2 < NBR) ? fcW[(size_t)(COUT + k2) * COUT + n] : 0.f;
            breg[ks][nt][0] = __float_as_uint(to_tf32(f1));
            breg[ks][nt][1] = __float_as_uint(to_tf32(f2));
        }

    // const zero K-columns 41..47 of EA (gather only writes 0..40)
    if (tid < 128) {
        #pragma unroll
        for (int j = NBR; j < 48; ++j) EA[tid * EASTR + j] = 0.f;
    }

    // prologue: indices for first tile
    {
        int e = blockIdx.x * 128 + (tid & 127);
        int v = 0;
        if (e < N_EDGES) v = (tid < 128) ? ei[e] : ei[N_EDGES + e];
        ib[tid] = v;
    }
    __syncthreads();

    for (int tile = blockIdx.x; tile < NTILES; tile += EGRID) {
        int e0 = tile * 128;
        int nv = min(128, N_EDGES - e0);

        // EA gather for CURRENT tile (cp.async) — latency covered by psum loads below
        {
            int m = tid >> 1;
            if (m < nv) {
                const float* src = edge_attr + (size_t)(e0 + m) * NBR;
                uint32_t db = smem_u32(EA + m * EASTR);
                if (tid & 1) {
                    #pragma unroll
                    for (int k = 20; k < NBR; ++k) CP4(db + k * 4u, src + k);
                } else {
                    #pragma unroll
                    for (int k = 0; k < 20; ++k) CP4(db + k * 4u, src + k);
                }
            }
        }
        CP_COMMIT();

        // index prefetch for next tile (regs)
        int idxpre = 0;
        {
            int tn = tile + EGRID;
            int e = tn * 128 + (tid & 127);
            if (tn < NTILES && e < N_EDGES) idxpre = (tid < 128) ? ei[e] : ei[N_EDGES + e];
        }

        // psum direct into accumulators: acc = P1[src] + P2[dst] at C-frag positions
        float acc[8][2][4];
        #pragma unroll
        for (int mi = 0; mi < 8; ++mi) {
            int m = mi * 16 + g;
            int s0 = ib[m],     d0 = ib[128 + m];
            int s1 = ib[m + 8], d1 = ib[128 + m + 8];
            #pragma unroll
            for (int nt = 0; nt < 2; ++nt) {
                int n0 = wid * 16 + nt * 8 + 2 * t;
                float2 pa = *(const float2*)&g_pcat[(size_t)s0 * 256 + n0];
                float2 pb = *(const float2*)&g_pcat[(size_t)d0 * 256 + 128 + n0];
                float2 pc = *(const float2*)&g_pcat[(size_t)s1 * 256 + n0];
                float2 pd = *(const float2*)&g_pcat[(size_t)d1 * 256 + 128 + n0];
                acc[mi][nt][0] = pa.x + pb.x;
                acc[mi][nt][1] = pa.y + pb.y;
                acc[mi][nt][2] = pc.x + pd.x;
                acc[mi][nt][3] = pc.y + pd.y;
            }
        }

        CP_WAIT0();
        __syncthreads();   // EA visible to all

        // MMA: 6 k-steps over edge_attr, accumulating onto psum
        #pragma unroll
        for (int ks = 0; ks < 6; ++ks) {
            #pragma unroll
            for (int mi = 0; mi < 8; ++mi) {
                const float* p = EA + (mi * 16 + g) * EASTR + ks * 8 + t;
                uint32_t a0 = __float_as_uint(p[0]);
                uint32_t a1 = __float_as_uint(p[8 * EASTR]);
                uint32_t a2 = __float_as_uint(p[4]);
                uint32_t a3 = __float_as_uint(p[8 * EASTR + 4]);
                mma_tf32(acc[mi][0], a0, a1, a2, a3, breg[ks][0][0], breg[ks][0][1]);
                mma_tf32(acc[mi][1], a0, a1, a2, a3, breg[ks][1][0], breg[ks][1][1]);
            }
        }
        __syncthreads();   // psum ib reads + EA reads done

        // stash next-tile indices
        ib[tid] = idxpre;

        // transpose acc -> SS as T[n][m]
        #pragma unroll
        for (int mi = 0; mi < 8; ++mi)
            #pragma unroll
            for (int nt = 0; nt < 2; ++nt) {
                int m = mi * 16 + g;
                int n = wid * 16 + nt * 8 + 2 * t;
                SS[n * SSTR + m]           = acc[mi][nt][0];
                SS[(n + 1) * SSTR + m]     = acc[mi][nt][1];
                SS[n * SSTR + m + 8]       = acc[mi][nt][2];
                SS[(n + 1) * SSTR + m + 8] = acc[mi][nt][3];
            }
        __syncthreads();

        // coalesced store + fused BN1 stats
        #pragma unroll 4
        for (int rr = 0; rr < 16; ++rr) {
            int n = wid * 16 + rr;
            float4 v = *(float4*)&SS[n * SSTR + lane * 4];
            bool ok = (lane * 4 < nv);
            if (ok) *(float4*)&g_gatedT[(size_t)n * N_EDGES + e0 + lane * 4] = v;
            float s = ok ? (v.x + v.y + v.z + v.w) : 0.f;
            float q = ok ? (v.x * v.x + v.y * v.y + v.z * v.z + v.w * v.w) : 0.f;
            #pragma unroll
            for (int o = 16; o > 0; o >>= 1) {
                s += __shfl_down_sync(0xffffffff, s, o);
                q += __shfl_down_sync(0xffffffff, q, o);
            }
            if (lane == 0) {
                atomicAdd(&g_bn1_acc[n], s);
                atomicAdd(&g_bn1_acc[COUT + n], q);
            }
        }
        __syncthreads();   // SS + ib stable for next iteration
    }
}

// ---------------- finalize BN1 ----------------
__global__ void finalize_bn1(const float* __restrict__ gg, const float* __restrict__ bb) {
    int c = threadIdx.x;
    const float invn = 1.f / (float)N_EDGES;
    float mu  = g_bn1_acc[c] * invn;
    float var = g_bn1_acc[COUT + c] * invn - mu * mu;
    float sc  = gg[c] * rsqrtf(var + EPSV);
    g_bn1_scale[c] = sc;
    g_bn1_shift[c] = bb[c] - mu * sc;
}

// ---------------- msg + scatter: 4 edges x 4 channels per thread ----------------
__global__ void msg_scatter_kernel(const int* __restrict__ ei) {
    int base = (blockIdx.x * blockDim.x + threadIdx.x) * 4;
    if (base >= N_EDGES) return;
    int c = blockIdx.y * 4;
    float4 F[4], C[4];
    #pragma unroll
    for (int j = 0; j < 4; ++j) {
        F[j] = *(const float4*)&g_gatedT[(size_t)(c + j) * N_EDGES + base];
        C[j] = *(const float4*)&g_gatedT[(size_t)(c + j + ATOM) * N_EDGES + base];
    }
    int srcs[4];
    #pragma unroll
    for (int ee = 0; ee < 4; ++ee) srcs[ee] = ei[base + ee];
    #pragma unroll
    for (int ee = 0; ee < 4; ++ee) {
        float m[4];
        #pragma unroll
        for (int j = 0; j < 4; ++j) {
            float gf = reinterpret_cast<const float*>(&F[j])[ee];
            float gc = reinterpret_cast<const float*>(&C[j])[ee];
            float nf = gf * g_bn1_scale[c + j]        + g_bn1_shift[c + j];
            float nc = gc * g_bn1_scale[c + j + ATOM] + g_bn1_shift[c + j + ATOM];
            float sg = 1.f / (1.f + expf(-nf));
            float sp = (nc > 20.f) ? nc : log1pf(expf(nc));
            m[j] = sg * sp;
        }
        float* p = &g_summed[(size_t)srcs[ee] * ATOM + c];
        asm volatile("red.global.add.v4.f32 [%0], {%1, %2, %3, %4};"
                     :: "l"(p), "f"(m[0]), "f"(m[1]), "f"(m[2]), "f"(m[3]) : "memory");
    }
}

// ---------------- BN2 ----------------
__global__ void bn2_stats_kernel() {
    __shared__ float ss[ATOM], sq[ATOM];
    if (threadIdx.x < ATOM) { ss[threadIdx.x] = 0.f; sq[threadIdx.x] = 0.f; }
    __syncthreads();
    int c = threadIdx.x & 63;
    float ls = 0.f, lq = 0.f;
    long long stride = (long long)gridDim.x * blockDim.x;
    for (long long i = (long long)blockIdx.x * blockDim.x + threadIdx.x;
         i < (long long)N_NODES * ATOM; i += stride) {
        float v = g_summed[i];
        ls += v; lq += v * v;
    }
    atomicAdd(&ss[c], ls);
    atomicAdd(&sq[c], lq);
    __syncthreads();
    if (threadIdx.x < ATOM) {
        atomicAdd(&g_bn2_acc[threadIdx.x], ss[threadIdx.x]);
        atomicAdd(&g_bn2_acc[ATOM + threadIdx.x], sq[threadIdx.x]);
    }
}

__global__ void finalize_bn2(const float* __restrict__ gg, const float* __restrict__ bb) {
    int c = threadIdx.x;
    const float invn = 1.f / (float)N_NODES;
    float mu  = g_bn2_acc[c] * invn;
    float var = g_bn2_acc[ATOM + c] * invn - mu * mu;
    float sc  = gg[c] * rsqrtf(var + EPSV);
    g_bn2_scale[c] = sc;
    g_bn2_shift[c] = bb[c] - mu * sc;
}

// ---------------- node stage ----------------
__global__ void node_kernel(const float* __restrict__ attW,
                            const float* __restrict__ attb,
                            float* __restrict__ out) {
    int n = blockIdx.x;
    int c = threadIdx.x;
    float v = g_summed[(size_t)n * ATOM + c] * g_bn2_scale[c] + g_bn2_shift[c];
    out[(size_t)n * ATOM + c] = v;
    float hv = v / (1.f + expf(-v));
    g_h[(size_t)n * ATOM + c] = hv;
    float p = hv * attW[c];
    #pragma unroll
    for (int o = 16; o > 0; o >>= 1) p += __shfl_down_sync(0xffffffff, p, o);
    __shared__ float r[2];
    if ((threadIdx.x & 31) == 0) r[threadIdx.x >> 5] = p;
    __syncthreads();
    if (threadIdx.x == 0) g_logits[n] = r[0] + r[1] + attb[0];
}

// ---------------- graph pooling ----------------
__device__ __forceinline__ int lbound(const int* a, int n, int key) {
    int lo = 0, hi = n;
    while (lo < hi) { int mid = (lo + hi) >> 1; if (a[mid] < key) lo = mid + 1; else hi = mid; }
    return lo;
}

__global__ void graph_kernel(const int* __restrict__ batch,
                             const float* __restrict__ outW,
                             const float* __restrict__ outb,
                             float* __restrict__ outp) {
    int g = blockIdx.x;
    __shared__ int s_lo, s_hi;
    __shared__ float red[256];
    __shared__ float s_max, s_den, s_rr[2];
    if (threadIdx.x == 0) {
        s_lo = lbound(batch, N_NODES, g);
        s_hi = lbound(batch, N_NODES, g + 1);
    }
    __syncthreads();
    int lo = s_lo, hi = s_hi;
    if (lo >= hi) {
        if (threadIdx.x == 0) outp[g] = outb[0];
        return;
    }
    float m = -INFINITY;
    for (int i = lo + threadIdx.x; i < hi; i += 256) m = fmaxf(m, g_logits[i]);
    red[threadIdx.x] = m;
    __syncthreads();
    for (int s = 128; s > 0; s >>= 1) {
        if (threadIdx.x < s) red[threadIdx.x] = fmaxf(red[threadIdx.x], red[threadIdx.x + s]);
        __syncthreads();
    }
    if (threadIdx.x == 0) s_max = red[0];
    __syncthreads();
    float mx = s_max;
    __syncthreads();
    float se = 0.f;
    for (int i = lo + threadIdx.x; i < hi; i += 256) se += expf(g_logits[i] - mx);
    red[threadIdx.x] = se;
    __syncthreads();
    for (int s = 128; s > 0; s >>= 1) {
        if (threadIdx.x < s) red[threadIdx.x] += red[threadIdx.x + s];
        __syncthreads();
    }
    if (threadIdx.x == 0) s_den = red[0];
    __syncthreads();
    float denom = s_den;
    __syncthreads();
    int q = threadIdx.x >> 6;
    int c = threadIdx.x & 63;
    float a = 0.f;
    for (int i = lo + q; i < hi; i += 4)
        a += expf(g_logits[i] - mx) * g_h[(size_t)i * ATOM + c];
    red[threadIdx.x] = a;
    __syncthreads();
    if (threadIdx.x < ATOM) {
        float crys = (red[c] + red[64 + c] + red[128 + c] + red[192 + c]) / denom;
        float p = crys * outW[c];
        #pragma unroll
        for (int o = 16; o > 0; o >>= 1) p += __shfl_down_sync(0xffffffff, p, o);
        if ((threadIdx.x & 31) == 0) s_rr[threadIdx.x >> 5] = p;
    }
    __syncthreads();
    if (threadIdx.x == 0) outp[g] = s_rr[0] + s_rr[1] + outb[0];
}

// ---------------- host launcher ----------------
extern "C" void kernel_launch(void* const* d_in, const int* in_sizes, int n_in,
                              void* d_out, int out_size) {
    const float *x, *edge_attr, *lower_f, *embW, *embb, *fcW, *fcb;
    const float *bn1g, *bn1b, *bn2g, *bn2b, *attW, *attb, *outW, *outb;
    const int *ei, *batch;

    if (in_sizes[3] == 2 * N_EDGES) {
        x        = (const float*)d_in[0];
        edge_attr= (const float*)d_in[1];
        lower_f  = (const float*)d_in[2];
        ei       = (const int*)  d_in[3];
        batch    = (const int*)  d_in[4];
        embW     = (const float*)d_in[5];
        embb     = (const float*)d_in[6];
        fcW      = (const float*)d_in[7];
        fcb      = (const float*)d_in[8];
        bn1g     = (const float*)d_in[9];
        bn1b     = (const float*)d_in[10];
        bn2g     = (const float*)d_in[11];
        bn2b     = (const float*)d_in[12];
        attW     = (const float*)d_in[13];
        attb     = (const float*)d_in[14];
        outW     = (const float*)d_in[15];
        outb     = (const float*)d_in[16];
    } else {
        x        = (const float*)d_in[0];
        edge_attr= (const float*)d_in[1];
        lower_f  = (const float*)d_in[2];
        embW     = (const float*)d_in[3];
        embb     = (const float*)d_in[4];
        fcW      = (const float*)d_in[5];
        fcb      = (const float*)d_in[6];
        bn1g     = (const float*)d_in[7];
        bn1b     = (const float*)d_in[8];
        bn2g     = (const float*)d_in[9];
        bn2b     = (const float*)d_in[10];
        attW     = (const float*)d_in[11];
        attb     = (const float*)d_in[12];
        outW     = (const float*)d_in[13];
        outb     = (const float*)d_in[14];
        ei       = (const int*)  d_in[15];
        batch    = (const int*)  d_in[16];
    }
    (void)fcb;  // fc bias cancels exactly through train-mode BN1

    float* out = (float*)d_out;

    void *p_summed = nullptr, *p_bn1 = nullptr, *p_bn2 = nullptr;
    cudaGetSymbolAddress(&p_summed, g_summed);
    cudaGetSymbolAddress(&p_bn1, g_bn1_acc);
    cudaGetSymbolAddress(&p_bn2, g_bn2_acc);
    cudaMemsetAsync(p_summed, 0, (size_t)N_NODES * ATOM * sizeof(float), 0);
    cudaMemsetAsync(p_bn1, 0, 2 * COUT * sizeof(float), 0);
    cudaMemsetAsync(p_bn2, 0, 2 * ATOM * sizeof(float), 0);

    // A: node embedding
    atomfea_kernel<<<(N_NODES + A_NPB - 1) / A_NPB, 256>>>(x, embW, embb, lower_f);

    // P: node-side partial products Pcat = atom_fea @ [W1|W2]
    cudaFuncSetAttribute(pcat_kernel, cudaFuncAttributeMaxDynamicSharedMemorySize, P_SMEM);
    pcat_kernel<<<(N_NODES + P_NPB - 1) / P_NPB, 256, P_SMEM>>>(fcW);

    // B1: edge GEMM (K=41), psum direct-to-acc, fused BN1; 2 CTAs/SM persistent
    cudaFuncSetAttribute(edge_gemm_mma, cudaFuncAttributeMaxDynamicSharedMemorySize, SM_BYTES);
    edge_gemm_mma<<<EGRID, 256, SM_BYTES>>>(edge_attr, ei, fcW);

    finalize_bn1<<<1, COUT>>>(bn1g, bn1b);

    // B2: message + scatter (float4 loads, v4 reductions)
    {
        dim3 grid((N_EDGES / 4 + 255) / 256, ATOM / 4);
        msg_scatter_kernel<<<grid, 256>>>(ei);
    }

    // BN2
    bn2_stats_kernel<<<512, 256>>>();
    finalize_bn2<<<1, ATOM>>>(bn2g, bn2b);

    // node stage -> atom_out output
    node_kernel<<<N_NODES, ATOM>>>(attW, attb, out);

    // graph pooling -> crys_fea
    graph_kernel<<<N_GRAPHS, 256>>>(batch, outW, outb, out + (size_t)N_NODES * ATOM);
}